// round 1
// baseline (speedup 1.0000x reference)
#include <cuda_runtime.h>
#include <math.h>

#define NN 50000
#define NE 1600000
#define NG 64
#define BN_EPS 1e-5f

// ---------------- scratch (static __device__, no allocation) ----------------
__device__ float  g_deg[NN];
__device__ float  g_dinv[NN];
__device__ int    g_rowptr[NN + 1];
__device__ int    g_cursor[NN];
__device__ int    g_col[NE];
__device__ float  g_H[(size_t)NN * 256];   // GEMM output (pre-aggregation)
__device__ float  g_A[(size_t)NN * 256];   // aggregation output / layer input
__device__ double g_bnsum[256];
__device__ double g_bnsumsq[256];
__device__ float  g_bns[256];              // BN scale
__device__ float  g_bnt[256];              // BN shift
__device__ float  g_pool[NG * 256];
__device__ float  g_cnt[NG];
__device__ float  g_fc1[NG * 1024];

// ---------------- init / degree / CSR ----------------
__global__ void k_prep() {
    int i = blockIdx.x * blockDim.x + threadIdx.x;
    if (i < NN) { g_deg[i] = 1.0f; g_cursor[i] = 0; }
    if (i < NG * 256) g_pool[i] = 0.0f;
    if (i < NG) g_cnt[i] = 0.0f;
}

__global__ void k_deg_count(const int* __restrict__ dst) {
    int e = blockIdx.x * blockDim.x + threadIdx.x;
    if (e < NE) atomicAdd(&g_deg[dst[e]], 1.0f);
}

__global__ void k_dinv() {
    int i = blockIdx.x * blockDim.x + threadIdx.x;
    if (i < NN) g_dinv[i] = rsqrtf(g_deg[i]);   // deg >= 1 always (self loop)
}

// single-block exclusive scan of (deg-1) -> rowptr
__global__ void k_rowptr() {
    __shared__ int sh[1024];
    __shared__ int carry;
    int tid = threadIdx.x;
    if (tid == 0) carry = 0;
    __syncthreads();
    for (int base = 0; base < NN; base += 1024) {
        int i = base + tid;
        int v = (i < NN) ? ((int)g_deg[i] - 1) : 0;
        sh[tid] = v;
        __syncthreads();
        for (int off = 1; off < 1024; off <<= 1) {
            int t = 0;
            if (tid >= off) t = sh[tid - off];
            __syncthreads();
            sh[tid] += t;
            __syncthreads();
        }
        if (i < NN) g_rowptr[i] = carry + sh[tid] - v;  // exclusive
        __syncthreads();
        if (tid == 0) carry += sh[1023];
        __syncthreads();
    }
    if (tid == 0) g_rowptr[NN] = carry;
}

__global__ void k_csr(const int* __restrict__ src, const int* __restrict__ dst) {
    int e = blockIdx.x * blockDim.x + threadIdx.x;
    if (e >= NE) return;
    int d = dst[e];
    int p = g_rowptr[d] + atomicAdd(&g_cursor[d], 1);
    g_col[p] = src[e];
}

// ---------------- fp32 tiled SGEMM: C[N,M] = A[N,K] @ B[K,M] ----------------
// requires M % 128 == 0, K % 16 == 0 (true for all our shapes)
__global__ __launch_bounds__(256) void k_sgemm(const float* __restrict__ A,
                                               const float* __restrict__ B,
                                               float* __restrict__ C,
                                               int N, int K, int M) {
    const int BM = 128, BN = 128, BK = 16;
    __shared__ float As[BK][BM];
    __shared__ float Bs[BK][BN];
    int bRow = blockIdx.y * BM;
    int bCol = blockIdx.x * BN;
    int tid = threadIdx.x;
    int tx = tid & 15, ty = tid >> 4;

    float acc[8][8];
#pragma unroll
    for (int i = 0; i < 8; i++)
#pragma unroll
        for (int j = 0; j < 8; j++) acc[i][j] = 0.0f;

    for (int k0 = 0; k0 < K; k0 += BK) {
        // load A tile 128x16 (512 float4, 2 per thread), store transposed
#pragma unroll
        for (int l = 0; l < 2; l++) {
            int idx = tid + l * 256;      // 0..511
            int r = idx >> 2;             // row in tile
            int kk = (idx & 3) * 4;
            float4 v = make_float4(0.f, 0.f, 0.f, 0.f);
            int row = bRow + r;
            if (row < N) v = *(const float4*)(A + (size_t)row * K + k0 + kk);
            As[kk + 0][r] = v.x; As[kk + 1][r] = v.y;
            As[kk + 2][r] = v.z; As[kk + 3][r] = v.w;
        }
        // load B tile 16x128 (512 float4)
#pragma unroll
        for (int l = 0; l < 2; l++) {
            int idx = tid + l * 256;
            int kk = idx >> 5;
            int c4 = (idx & 31) * 4;
            float4 v = *(const float4*)(B + (size_t)(k0 + kk) * M + bCol + c4);
            *(float4*)&Bs[kk][c4] = v;
        }
        __syncthreads();
#pragma unroll
        for (int kk = 0; kk < BK; kk++) {
            float ra[8], rb[8];
            *(float4*)&ra[0] = *(const float4*)&As[kk][ty * 8];
            *(float4*)&ra[4] = *(const float4*)&As[kk][ty * 8 + 4];
            *(float4*)&rb[0] = *(const float4*)&Bs[kk][tx * 8];
            *(float4*)&rb[4] = *(const float4*)&Bs[kk][tx * 8 + 4];
#pragma unroll
            for (int i = 0; i < 8; i++)
#pragma unroll
                for (int j = 0; j < 8; j++) acc[i][j] += ra[i] * rb[j];
        }
        __syncthreads();
    }
#pragma unroll
    for (int i = 0; i < 8; i++) {
        int row = bRow + ty * 8 + i;
        if (row >= N) continue;
        float* cp = C + (size_t)row * M + bCol + tx * 8;
        *(float4*)cp = make_float4(acc[i][0], acc[i][1], acc[i][2], acc[i][3]);
        *(float4*)(cp + 4) = make_float4(acc[i][4], acc[i][5], acc[i][6], acc[i][7]);
    }
}

// ---------------- CSR gather aggregation (warp per dst node) ----------------
// O[d] = dinv[d] * ( sum_{s in nbr(d)} dinv[s]*H[s] + dinv[d]*H[d] ) + bias
template <int NV4>   // float4s per lane: C = NV4*128
__global__ void k_agg(const float* __restrict__ H, float* __restrict__ O,
                      const float* __restrict__ bias) {
    const int C = NV4 * 128;
    int w = (blockIdx.x * blockDim.x + threadIdx.x) >> 5;
    if (w >= NN) return;
    int lane = threadIdx.x & 31;
    float di = g_dinv[w];

    float4 acc[NV4];
    const float4* selfp = (const float4*)(H + (size_t)w * C);
#pragma unroll
    for (int v = 0; v < NV4; v++) {
        float4 h = selfp[lane + 32 * v];
        acc[v] = make_float4(h.x * di, h.y * di, h.z * di, h.w * di);
    }
    int p = g_rowptr[w], e = g_rowptr[w + 1];
    for (; p < e; ++p) {
        int s = g_col[p];
        float ws = g_dinv[s];
        const float4* hp = (const float4*)(H + (size_t)s * C);
#pragma unroll
        for (int v = 0; v < NV4; v++) {
            float4 h = hp[lane + 32 * v];
            acc[v].x += ws * h.x; acc[v].y += ws * h.y;
            acc[v].z += ws * h.z; acc[v].w += ws * h.w;
        }
    }
#pragma unroll
    for (int v = 0; v < NV4; v++) {
        int c = (lane + 32 * v) * 4;
        float4 bb = *(const float4*)(bias + c);
        float4 o = make_float4(acc[v].x * di + bb.x, acc[v].y * di + bb.y,
                               acc[v].z * di + bb.z, acc[v].w * di + bb.w);
        *(float4*)(O + (size_t)w * C + c) = o;
    }
}

// ---------------- BatchNorm (training-mode, biased var) + ReLU ----------------
__global__ void k_bnzero() {
    int c = threadIdx.x;   // 256 threads
    g_bnsum[c] = 0.0; g_bnsumsq[c] = 0.0;
}

__global__ void k_bnstats(const float* __restrict__ h, int C) {
    int t = blockIdx.x * blockDim.x + threadIdx.x;
    if (t >= C * 64) return;
    int c = t & (C - 1);
    int p = t / C;
    float s = 0.f, q = 0.f;
    for (int r = p; r < NN; r += 64) {
        float x = h[(size_t)r * C + c];
        s += x; q += x * x;
    }
    atomicAdd(&g_bnsum[c], (double)s);
    atomicAdd(&g_bnsumsq[c], (double)q);
}

__global__ void k_bnfin(const float* __restrict__ gamma,
                        const float* __restrict__ beta, int C) {
    int c = blockIdx.x * blockDim.x + threadIdx.x;
    if (c >= C) return;
    double m = g_bnsum[c] / (double)NN;
    double v = g_bnsumsq[c] / (double)NN - m * m;
    float sc = gamma[c] * rsqrtf((float)v + BN_EPS);
    g_bns[c] = sc;
    g_bnt[c] = beta[c] - (float)m * sc;
}

__global__ void k_bnapply(float* __restrict__ h, int C) {
    size_t i = (size_t)blockIdx.x * blockDim.x + threadIdx.x;
    if (i >= (size_t)NN * C) return;
    int c = (int)(i & (C - 1));
    float x = h[i] * g_bns[c] + g_bnt[c];
    h[i] = fmaxf(x, 0.0f);
}

// ---------------- global mean pool ----------------
__global__ void k_cnt(const int* __restrict__ batch) {
    int i = blockIdx.x * blockDim.x + threadIdx.x;
    if (i < NN) atomicAdd(&g_cnt[batch[i]], 1.0f);
}

__global__ void k_pool(const float* __restrict__ h, const int* __restrict__ batch) {
    size_t i = (size_t)blockIdx.x * blockDim.x + threadIdx.x;
    if (i >= (size_t)NN * 256) return;
    int n = (int)(i >> 8);
    int c = (int)(i & 255);
    atomicAdd(&g_pool[batch[n] * 256 + c], h[i]);
}

__global__ void k_poolfin() {
    int i = blockIdx.x * blockDim.x + threadIdx.x;
    if (i >= NG * 256) return;
    int b = i >> 8;
    g_pool[i] *= 1.0f / fmaxf(g_cnt[b], 1.0f);
}

// ---------------- FC head ----------------
__global__ void k_fc1(const float* __restrict__ Wf0, const float* __restrict__ bf0) {
    int t = blockIdx.x * blockDim.x + threadIdx.x;
    if (t >= NG * 1024) return;
    int b = t >> 10, j = t & 1023;
    float s = bf0[j];
    const float* g = g_pool + b * 256;
    for (int c = 0; c < 256; c++) s += g[c] * Wf0[c * 1024 + j];
    g_fc1[t] = fmaxf(s, 0.0f);
}

__global__ void k_fc2(const float* __restrict__ Wf1, const float* __restrict__ bf1,
                      float* __restrict__ out) {
    int t = blockIdx.x * blockDim.x + threadIdx.x;
    if (t >= NG * 128) return;
    int b = t >> 7, j = t & 127;
    float s = bf1[j];
    const float* g = g_fc1 + b * 1024;
    for (int c = 0; c < 1024; c++) s += g[c] * Wf1[c * 128 + j];
    out[t] = s;
}

// ---------------- launcher ----------------
extern "C" void kernel_launch(void* const* d_in, const int* in_sizes, int n_in,
                              void* d_out, int out_size) {
    const float* x     = (const float*)d_in[0];
    const int*   ei    = (const int*)d_in[1];
    const int*   batch = (const int*)d_in[2];
    const float* Wg0 = (const float*)d_in[3];
    const float* bg0 = (const float*)d_in[4];
    const float* gm0 = (const float*)d_in[5];
    const float* bt0 = (const float*)d_in[6];
    const float* Wg1 = (const float*)d_in[7];
    const float* bg1 = (const float*)d_in[8];
    const float* gm1 = (const float*)d_in[9];
    const float* bt1 = (const float*)d_in[10];
    const float* Wg2 = (const float*)d_in[11];
    const float* bg2 = (const float*)d_in[12];
    const float* gm2 = (const float*)d_in[13];
    const float* bt2 = (const float*)d_in[14];
    const float* Wf0 = (const float*)d_in[15];
    const float* bf0 = (const float*)d_in[16];
    const float* Wf1 = (const float*)d_in[17];
    const float* bf1 = (const float*)d_in[18];
    float* out = (float*)d_out;

    const int* src = ei;           // edge_index[0]
    const int* dst = ei + NE;      // edge_index[1]

    float* H; cudaGetSymbolAddress((void**)&H, g_H);
    float* A; cudaGetSymbolAddress((void**)&A, g_A);

    // graph structure (rebuilt each call; reused by all 3 layers)
    k_prep<<<(NN + 255) / 256, 256>>>();
    k_deg_count<<<(NE + 255) / 256, 256>>>(dst);
    k_dinv<<<(NN + 255) / 256, 256>>>();
    k_rowptr<<<1, 1024>>>();
    k_csr<<<(NE + 255) / 256, 256>>>(src, dst);

    const int gy = (NN + 127) / 128;

    // ---- layer 0: x[50000,1280] @ Wg0[1280,128]
    k_sgemm<<<dim3(1, gy), 256>>>(x, Wg0, H, NN, 1280, 128);
    k_agg<1><<<(NN * 32 + 255) / 256, 256>>>(H, A, bg0);
    k_bnzero<<<1, 256>>>();
    k_bnstats<<<(128 * 64 + 255) / 256, 256>>>(A, 128);
    k_bnfin<<<1, 128>>>(gm0, bt0, 128);
    k_bnapply<<<((size_t)NN * 128 + 255) / 256, 256>>>(A, 128);

    // ---- layer 1: A[50000,128] @ Wg1[128,256]
    k_sgemm<<<dim3(2, gy), 256>>>(A, Wg1, H, NN, 128, 256);
    k_agg<2><<<(NN * 32 + 255) / 256, 256>>>(H, A, bg1);
    k_bnzero<<<1, 256>>>();
    k_bnstats<<<(256 * 64 + 255) / 256, 256>>>(A, 256);
    k_bnfin<<<1, 256>>>(gm1, bt1, 256);
    k_bnapply<<<((size_t)NN * 256 + 255) / 256, 256>>>(A, 256);

    // ---- layer 2: A[50000,256] @ Wg2[256,256]
    k_sgemm<<<dim3(2, gy), 256>>>(A, Wg2, H, NN, 256, 256);
    k_agg<2><<<(NN * 32 + 255) / 256, 256>>>(H, A, bg2);
    k_bnzero<<<1, 256>>>();
    k_bnstats<<<(256 * 64 + 255) / 256, 256>>>(A, 256);
    k_bnfin<<<1, 256>>>(gm2, bt2, 256);
    k_bnapply<<<((size_t)NN * 256 + 255) / 256, 256>>>(A, 256);

    // ---- pool + FC head
    k_cnt<<<(NN + 255) / 256, 256>>>(batch);
    k_pool<<<((size_t)NN * 256 + 255) / 256, 256>>>(A, batch);
    k_poolfin<<<(NG * 256 + 255) / 256, 256>>>();
    k_fc1<<<(NG * 1024 + 255) / 256, 256>>>(Wf0, bf0);
    k_fc2<<<(NG * 128 + 255) / 256, 256>>>(Wf1, bf1, out);
}

// round 3
// speedup vs baseline: 1.3334x; 1.3334x over previous
#include <cuda_runtime.h>
#include <mma.h>
#include <math.h>

using namespace nvcuda;

#define NN 50000
#define NNP 50048           // 391 * 128, padded row count for GEMM tiles
#define NE 1600000
#define NG 64
#define BN_EPS 1e-5f

// ---------------- scratch (static __device__, no allocation) ----------------
__device__ float  g_deg[NN];
__device__ float  g_dinv[NN];
__device__ int    g_rowptr[NN + 1];
__device__ int    g_cursor[NN];
__device__ int    g_col[NE];
__device__ int    g_blksum[64];
__device__ int    g_blkoff[64];
__device__ int    g_gstart[NG + 1];
__device__ float  g_H[(size_t)NNP * 256];   // GEMM output (pre-aggregation), padded
__device__ float  g_A[(size_t)NNP * 256];   // aggregation output / layer input, padded
__device__ double g_bnsum[256];
__device__ double g_bnsumsq[256];
__device__ float  g_bns[256];               // BN scale
__device__ float  g_bnt[256];               // BN shift
__device__ float  g_pool[NG * 256];
__device__ float  g_fc1[NG * 1024];

// ---------------- init / degree ----------------
__global__ void k_prep() {
    int i = blockIdx.x * blockDim.x + threadIdx.x;
    if (i < NN) { g_deg[i] = 1.0f; g_cursor[i] = 0; }
}

__global__ void k_deg_count(const int* __restrict__ dst) {
    int e = blockIdx.x * blockDim.x + threadIdx.x;
    if (e < NE) atomicAdd(&g_deg[dst[e]], 1.0f);
}

__global__ void k_dinv() {
    int i = blockIdx.x * blockDim.x + threadIdx.x;
    if (i < NN) g_dinv[i] = rsqrtf(g_deg[i]);   // deg >= 1 always (self loop)
}

// ---------------- 3-phase exclusive scan of (deg-1) -> rowptr ----------------
// phase 1: 49 blocks x 1024: per-block exclusive scan, write partials + block sums
__global__ void k_scan1() {
    __shared__ int sh[1024];
    int tid = threadIdx.x;
    int i = blockIdx.x * 1024 + tid;
    int v = (i < NN) ? ((int)g_deg[i] - 1) : 0;
    sh[tid] = v;
    __syncthreads();
    for (int off = 1; off < 1024; off <<= 1) {
        int t = (tid >= off) ? sh[tid - off] : 0;
        __syncthreads();
        sh[tid] += t;
        __syncthreads();
    }
    if (i < NN) g_rowptr[i] = sh[tid] - v;     // block-local exclusive
    if (tid == 1023) g_blksum[blockIdx.x] = sh[1023];
}
// phase 2: serial scan of 49 block sums (tiny)
__global__ void k_scan2(int nblk) {
    if (threadIdx.x != 0) return;
    int acc = 0;
    for (int b = 0; b < nblk; b++) { g_blkoff[b] = acc; acc += g_blksum[b]; }
    g_rowptr[NN] = acc;
}
// phase 3: add block offsets
__global__ void k_scan3() {
    int i = blockIdx.x * 1024 + threadIdx.x;
    if (i < NN) g_rowptr[i] += g_blkoff[blockIdx.x];
}

__global__ void k_csr(const int* __restrict__ src, const int* __restrict__ dst) {
    int e = blockIdx.x * blockDim.x + threadIdx.x;
    if (e >= NE) return;
    int d = dst[e];
    int p = g_rowptr[d] + atomicAdd(&g_cursor[d], 1);
    g_col[p] = src[e];
}

// ---------------- tf32 tensor-core GEMM: C[NNP,M] = A[*,K] @ B[K,M] ----------
// BM=128, BN=128, BK=16. 8 warps: warp_m = wid&3 (32 rows), warp_n = wid>>2 (64 cols)
// A rows >= NA are treated as zero. C store is unpredicated into padded scratch.
#define AST 20   // As row stride (16 + 4 pad floats)
__global__ __launch_bounds__(256) void k_gemm_tf32(const float* __restrict__ A,
                                                   const float* __restrict__ B,
                                                   float* __restrict__ C,
                                                   int NA, int K, int M) {
    __shared__ float As[128 * AST];
    __shared__ float Bs[16 * 128];
    const int bRow = blockIdx.y * 128;
    const int bCol = blockIdx.x * 128;
    const int tid = threadIdx.x;
    const int wid = tid >> 5;
    const int wm = wid & 3;        // 0..3 -> 32-row slab
    const int wn = wid >> 2;       // 0..1 -> 64-col slab

    wmma::fragment<wmma::accumulator, 16, 16, 8, float> acc[2][4];
#pragma unroll
    for (int i = 0; i < 2; i++)
#pragma unroll
        for (int j = 0; j < 4; j++) wmma::fill_fragment(acc[i][j], 0.0f);

    for (int k0 = 0; k0 < K; k0 += 16) {
        // A tile: 128x16 = 512 float4
#pragma unroll
        for (int l = 0; l < 2; l++) {
            int f = tid + l * 256;
            int row = f >> 2;
            int c4 = (f & 3) * 4;
            int gRow = bRow + row;
            float4 v = make_float4(0.f, 0.f, 0.f, 0.f);
            if (gRow < NA) v = *(const float4*)(A + (size_t)gRow * K + k0 + c4);
            *(float4*)&As[row * AST + c4] = v;
        }
        // B tile: 16x128 = 512 float4
#pragma unroll
        for (int l = 0; l < 2; l++) {
            int f = tid + l * 256;
            int kk = f >> 5;
            int c4 = (f & 31) * 4;
            *(float4*)&Bs[kk * 128 + c4] =
                *(const float4*)(B + (size_t)(k0 + kk) * M + bCol + c4);
        }
        __syncthreads();
#pragma unroll
        for (int kk = 0; kk < 16; kk += 8) {
            wmma::fragment<wmma::matrix_a, 16, 16, 8, wmma::precision::tf32, wmma::row_major> af[2];
            wmma::fragment<wmma::matrix_b, 16, 16, 8, wmma::precision::tf32, wmma::row_major> bf[4];
#pragma unroll
            for (int i = 0; i < 2; i++) {
                wmma::load_matrix_sync(af[i], &As[(wm * 32 + i * 16) * AST + kk], AST);
#pragma unroll
                for (int t = 0; t < af[i].num_elements; t++)
                    af[i].x[t] = wmma::__float_to_tf32(af[i].x[t]);
            }
#pragma unroll
            for (int j = 0; j < 4; j++) {
                wmma::load_matrix_sync(bf[j], &Bs[kk * 128 + wn * 64 + j * 16], 128);
#pragma unroll
                for (int t = 0; t < bf[j].num_elements; t++)
                    bf[j].x[t] = wmma::__float_to_tf32(bf[j].x[t]);
            }
#pragma unroll
            for (int i = 0; i < 2; i++)
#pragma unroll
                for (int j = 0; j < 4; j++)
                    wmma::mma_sync(acc[i][j], af[i], bf[j], acc[i][j]);
        }
        __syncthreads();
    }
#pragma unroll
    for (int i = 0; i < 2; i++)
#pragma unroll
        for (int j = 0; j < 4; j++) {
            int row0 = bRow + wm * 32 + i * 16;
            int col0 = bCol + wn * 64 + j * 16;
            wmma::store_matrix_sync(C + (size_t)row0 * M + col0, acc[i][j], M,
                                    wmma::mem_row_major);
        }
}

// ---------------- CSR gather aggregation (warp per dst node) ----------------
// O[d] = dinv[d] * ( sum_{s in nbr(d)} dinv[s]*H[s] + dinv[d]*H[d] ) + bias
template <int NV4>   // float4s per lane: C = NV4*128
__global__ void k_agg(const float* __restrict__ H, float* __restrict__ O,
                      const float* __restrict__ bias) {
    const int C = NV4 * 128;
    int w = (blockIdx.x * blockDim.x + threadIdx.x) >> 5;
    if (w >= NN) return;
    int lane = threadIdx.x & 31;
    float di = g_dinv[w];

    float4 acc[NV4];
    const float4* selfp = (const float4*)(H + (size_t)w * C);
#pragma unroll
    for (int v = 0; v < NV4; v++) {
        float4 h = selfp[lane + 32 * v];
        acc[v] = make_float4(h.x * di, h.y * di, h.z * di, h.w * di);
    }
    int p = g_rowptr[w], e = g_rowptr[w + 1];
    for (; p < e; ++p) {
        int s = g_col[p];
        float ws = g_dinv[s];
        const float4* hp = (const float4*)(H + (size_t)s * C);
#pragma unroll
        for (int v = 0; v < NV4; v++) {
            float4 h = hp[lane + 32 * v];
            acc[v].x += ws * h.x; acc[v].y += ws * h.y;
            acc[v].z += ws * h.z; acc[v].w += ws * h.w;
        }
    }
#pragma unroll
    for (int v = 0; v < NV4; v++) {
        int c = (lane + 32 * v) * 4;
        float4 bb = *(const float4*)(bias + c);
        float4 o = make_float4(acc[v].x * di + bb.x, acc[v].y * di + bb.y,
                               acc[v].z * di + bb.z, acc[v].w * di + bb.w);
        *(float4*)(O + (size_t)w * C + c) = o;
    }
}

// ---------------- BatchNorm (training-mode, biased var) + ReLU ----------------
__global__ void k_bnzero() {
    int c = threadIdx.x;   // 256 threads
    g_bnsum[c] = 0.0; g_bnsumsq[c] = 0.0;
}

__global__ void k_bnstats(const float* __restrict__ h, int C) {
    int t = blockIdx.x * blockDim.x + threadIdx.x;
    if (t >= C * 64) return;
    int c = t & (C - 1);
    int p = t / C;
    float s = 0.f, q = 0.f;
    for (int r = p; r < NN; r += 64) {
        float x = h[(size_t)r * C + c];
        s += x; q += x * x;
    }
    atomicAdd(&g_bnsum[c], (double)s);
    atomicAdd(&g_bnsumsq[c], (double)q);
}

__global__ void k_bnfin(const float* __restrict__ gamma,
                        const float* __restrict__ beta, int C) {
    int c = blockIdx.x * blockDim.x + threadIdx.x;
    if (c >= C) return;
    double m = g_bnsum[c] / (double)NN;
    double v = g_bnsumsq[c] / (double)NN - m * m;
    float sc = gamma[c] * rsqrtf((float)v + BN_EPS);
    g_bns[c] = sc;
    g_bnt[c] = beta[c] - (float)m * sc;
}

__global__ void k_bnapply(float* __restrict__ h, int C) {
    size_t i = (size_t)blockIdx.x * blockDim.x + threadIdx.x;
    if (i >= (size_t)NN * C) return;
    int c = (int)(i & (C - 1));
    float x = h[i] * g_bns[c] + g_bnt[c];
    h[i] = fmaxf(x, 0.0f);
}

// ---------------- global mean pool (sorted batch -> contiguous ranges) -------
__global__ void k_bounds(const int* __restrict__ batch) {
    int g = threadIdx.x;            // 0..NG (65 threads)
    if (g > NG) return;
    int lo = 0, hi = NN;            // lower_bound of g
    while (lo < hi) { int mid = (lo + hi) >> 1; if (batch[mid] < g) lo = mid + 1; else hi = mid; }
    g_gstart[g] = lo;
}

__global__ void k_pool(const float* __restrict__ h) {
    int b = blockIdx.x;             // 64 blocks, 256 threads
    int c = threadIdx.x;
    int st = g_gstart[b], en = g_gstart[b + 1];
    float s = 0.f;
    for (int r = st; r < en; r++) s += h[(size_t)r * 256 + c];
    g_pool[b * 256 + c] = s / fmaxf((float)(en - st), 1.0f);
}

// ---------------- FC head ----------------
__global__ void k_fc1(const float* __restrict__ Wf0, const float* __restrict__ bf0) {
    int t = blockIdx.x * blockDim.x + threadIdx.x;
    if (t >= NG * 1024) return;
    int b = t >> 10, j = t & 1023;
    float s = bf0[j];
    const float* g = g_pool + b * 256;
    for (int c = 0; c < 256; c++) s += g[c] * Wf0[c * 1024 + j];
    g_fc1[t] = fmaxf(s, 0.0f);
}

__global__ void k_fc2(const float* __restrict__ Wf1, const float* __restrict__ bf1,
                      float* __restrict__ out) {
    int t = blockIdx.x * blockDim.x + threadIdx.x;
    if (t >= NG * 128) return;
    int b = t >> 7, j = t & 127;
    float s = bf1[j];
    const float* g = g_fc1 + b * 1024;
    for (int c = 0; c < 1024; c++) s += g[c] * Wf1[c * 128 + j];
    out[t] = s;
}

// ---------------- launcher ----------------
extern "C" void kernel_launch(void* const* d_in, const int* in_sizes, int n_in,
                              void* d_out, int out_size) {
    const float* x     = (const float*)d_in[0];
    const int*   ei    = (const int*)d_in[1];
    const int*   batch = (const int*)d_in[2];
    const float* Wg0 = (const float*)d_in[3];
    const float* bg0 = (const float*)d_in[4];
    const float* gm0 = (const float*)d_in[5];
    const float* bt0 = (const float*)d_in[6];
    const float* Wg1 = (const float*)d_in[7];
    const float* bg1 = (const float*)d_in[8];
    const float* gm1 = (const float*)d_in[9];
    const float* bt1 = (const float*)d_in[10];
    const float* Wg2 = (const float*)d_in[11];
    const float* bg2 = (const float*)d_in[12];
    const float* gm2 = (const float*)d_in[13];
    const float* bt2 = (const float*)d_in[14];
    const float* Wf0 = (const float*)d_in[15];
    const float* bf0 = (const float*)d_in[16];
    const float* Wf1 = (const float*)d_in[17];
    const float* bf1 = (const float*)d_in[18];
    float* out = (float*)d_out;

    const int* src = ei;           // edge_index[0]
    const int* dst = ei + NE;      // edge_index[1]

    float* H; cudaGetSymbolAddress((void**)&H, g_H);
    float* A; cudaGetSymbolAddress((void**)&A, g_A);

    const int NBLK = (NN + 1023) / 1024;   // 49

    // graph structure (rebuilt each call; reused by all 3 layers)
    k_prep<<<(NN + 255) / 256, 256>>>();
    k_deg_count<<<(NE + 255) / 256, 256>>>(dst);
    k_dinv<<<(NN + 255) / 256, 256>>>();
    k_scan1<<<NBLK, 1024>>>();
    k_scan2<<<1, 32>>>(NBLK);
    k_scan3<<<NBLK, 1024>>>();
    k_csr<<<(NE + 255) / 256, 256>>>(src, dst);
    k_bounds<<<1, 96>>>(batch);

    const int gy = NNP / 128;   // 391

    // ---- layer 0: x[50000,1280] @ Wg0[1280,128]
    k_gemm_tf32<<<dim3(1, gy), 256>>>(x, Wg0, H, NN, 1280, 128);
    k_agg<1><<<(NN * 32 + 255) / 256, 256>>>(H, A, bg0);
    k_bnzero<<<1, 256>>>();
    k_bnstats<<<(128 * 64 + 255) / 256, 256>>>(A, 128);
    k_bnfin<<<1, 128>>>(gm0, bt0, 128);
    k_bnapply<<<((size_t)NN * 128 + 255) / 256, 256>>>(A, 128);

    // ---- layer 1: A[50048,128] @ Wg1[128,256]   (pad rows are zero / ignored)
    k_gemm_tf32<<<dim3(2, gy), 256>>>(A, Wg1, H, NNP, 128, 256);
    k_agg<2><<<(NN * 32 + 255) / 256, 256>>>(H, A, bg1);
    k_bnzero<<<1, 256>>>();
    k_bnstats<<<(256 * 64 + 255) / 256, 256>>>(A, 256);
    k_bnfin<<<1, 256>>>(gm1, bt1, 256);
    k_bnapply<<<((size_t)NN * 256 + 255) / 256, 256>>>(A, 256);

    // ---- layer 2: A[50048,256] @ Wg2[256,256]
    k_gemm_tf32<<<dim3(2, gy), 256>>>(A, Wg2, H, NNP, 256, 256);
    k_agg<2><<<(NN * 32 + 255) / 256, 256>>>(H, A, bg2);
    k_bnzero<<<1, 256>>>();
    k_bnstats<<<(256 * 64 + 255) / 256, 256>>>(A, 256);
    k_bnfin<<<1, 256>>>(gm2, bt2, 256);
    k_bnapply<<<((size_t)NN * 256 + 255) / 256, 256>>>(A, 256);

    // ---- pool + FC head
    k_pool<<<NG, 256>>>(A);
    k_fc1<<<(NG * 1024 + 255) / 256, 256>>>(Wf0, bf0);
    k_fc2<<<(NG * 128 + 255) / 256, 256>>>(Wf1, bf1, out);
}

// round 7
// speedup vs baseline: 1.6881x; 1.2660x over previous
#include <cuda_runtime.h>
#include <cuda_fp16.h>
#include <mma.h>
#include <math.h>
#include <cstdint>

using namespace nvcuda;

#define NN 50000
#define NNP 50048           // 391 * 128, padded row count for GEMM tiles
#define NE 1600000
#define NG 64
#define BN_EPS 1e-5f

// ---------------- scratch (static __device__, no allocation) ----------------
__device__ float  g_deg[NN];
__device__ float  g_dinv[NN];
__device__ int    g_rowptr[NN + 1];
__device__ int    g_cursor[NN];
__device__ int    g_col[NE];
__device__ int    g_blksum[64];
__device__ int    g_blkoff[64];
__device__ int    g_gstart[NG + 1];
__device__ __half g_H[(size_t)NNP * 256];   // GEMM output (fp16, pre-aggregation)
__device__ float  g_A[(size_t)NNP * 256];   // aggregation output / layer input
__device__ double g_bnsum[256];
__device__ double g_bnsumsq[256];
__device__ float  g_bns[256];               // BN scale
__device__ float  g_bnt[256];               // BN shift
__device__ float  g_pool[NG * 256];
__device__ float  g_fc1[NG * 1024];

// ---------------- cp.async helper (plain 16B form only) ----------------
__device__ __forceinline__ void cp16(void* smem, const void* gmem) {
    unsigned int s = (unsigned int)__cvta_generic_to_shared(smem);
    asm volatile("cp.async.cg.shared.global [%0], [%1], 16;\n"
                 :: "r"(s), "l"(gmem));
}
#define CP_COMMIT() asm volatile("cp.async.commit_group;\n" ::: "memory")
#define CP_WAIT(N)  asm volatile("cp.async.wait_group %0;\n" :: "n"(N) : "memory")

// ---------------- init / degree ----------------
__global__ void k_prep() {
    int i = blockIdx.x * blockDim.x + threadIdx.x;
    if (i < NN) { g_deg[i] = 1.0f; g_cursor[i] = 0; }
}

__global__ void k_deg_count(const int* __restrict__ dst) {
    int e = blockIdx.x * blockDim.x + threadIdx.x;
    if (e < NE) atomicAdd(&g_deg[dst[e]], 1.0f);
}

__global__ void k_dinv() {
    int i = blockIdx.x * blockDim.x + threadIdx.x;
    if (i < NN) g_dinv[i] = rsqrtf(g_deg[i]);   // deg >= 1 always (self loop)
}

// ---------------- 3-phase exclusive scan of (deg-1) -> rowptr ----------------
__global__ void k_scan1() {
    __shared__ int sh[1024];
    int tid = threadIdx.x;
    int i = blockIdx.x * 1024 + tid;
    int v = (i < NN) ? ((int)g_deg[i] - 1) : 0;
    sh[tid] = v;
    __syncthreads();
    for (int off = 1; off < 1024; off <<= 1) {
        int t = (tid >= off) ? sh[tid - off] : 0;
        __syncthreads();
        sh[tid] += t;
        __syncthreads();
    }
    if (i < NN) g_rowptr[i] = sh[tid] - v;     // block-local exclusive
    if (tid == 1023) g_blksum[blockIdx.x] = sh[1023];
}
__global__ void k_scan2(int nblk) {
    if (threadIdx.x != 0) return;
    int acc = 0;
    for (int b = 0; b < nblk; b++) { g_blkoff[b] = acc; acc += g_blksum[b]; }
    g_rowptr[NN] = acc;
}
__global__ void k_scan3() {
    int i = blockIdx.x * 1024 + threadIdx.x;
    if (i < NN) g_rowptr[i] += g_blkoff[blockIdx.x];
}

__global__ void k_csr(const int* __restrict__ src, const int* __restrict__ dst) {
    int e = blockIdx.x * blockDim.x + threadIdx.x;
    if (e >= NE) return;
    int d = dst[e];
    int p = g_rowptr[d] + atomicAdd(&g_cursor[d], 1);
    g_col[p] = src[e];
}

// ------- tf32 tensor-core GEMM, cp.async double-buffered, fp16 output -------
// C[NNP,M](fp16) = A[*,K](fp32) @ B[K,M](fp32).  BM=128, BN=128, BK=16.
// Rows >= NA are clamped to row 0 (garbage lands only in pad rows, never read).
#define AST 20   // As row stride (16 + 4 pad floats)
__global__ __launch_bounds__(256) void k_gemm_tf32(const float* __restrict__ A,
                                                   const float* __restrict__ B,
                                                   __half* __restrict__ C,
                                                   int NA, int K, int M) {
    __shared__ float As[2][128 * AST];
    __shared__ float Bs[2][16 * 128];
    __shared__ float stg[8][16 * 16 + 8];
    const int bRow = blockIdx.y * 128;
    const int bCol = blockIdx.x * 128;
    const int tid = threadIdx.x;
    const int wid = tid >> 5;
    const int lane = tid & 31;
    const int wm = wid & 3;
    const int wn = wid >> 2;

    wmma::fragment<wmma::accumulator, 16, 16, 8, float> acc[2][4];
#pragma unroll
    for (int i = 0; i < 2; i++)
#pragma unroll
        for (int j = 0; j < 4; j++) wmma::fill_fragment(acc[i][j], 0.0f);

    auto issue = [&](int t, int stage) {
        int k0 = t * 16;
#pragma unroll
        for (int l = 0; l < 2; l++) {          // A tile: 128x16
            int f = tid + l * 256;
            int row = f >> 2;
            int c4 = (f & 3) * 4;
            int gRow = bRow + row;
            if (gRow >= NA) gRow = 0;          // clamp: pad-row garbage unread
            cp16(&As[stage][row * AST + c4], A + (size_t)gRow * K + k0 + c4);
        }
#pragma unroll
        for (int l = 0; l < 2; l++) {          // B tile: 16x128
            int f = tid + l * 256;
            int kk = f >> 5;
            int c4 = (f & 31) * 4;
            cp16(&Bs[stage][kk * 128 + c4],
                 B + (size_t)(k0 + kk) * M + bCol + c4);
        }
    };

    const int T = K / 16;
    issue(0, 0);
    CP_COMMIT();

    for (int t = 0; t < T; t++) {
        if (t + 1 < T) {
            issue(t + 1, (t + 1) & 1);
            CP_COMMIT();
            CP_WAIT(1);
        } else {
            CP_WAIT(0);
        }
        __syncthreads();
        const float* as = As[t & 1];
        const float* bs = Bs[t & 1];
#pragma unroll
        for (int kk = 0; kk < 16; kk += 8) {
            wmma::fragment<wmma::matrix_a, 16, 16, 8, wmma::precision::tf32, wmma::row_major> af[2];
            wmma::fragment<wmma::matrix_b, 16, 16, 8, wmma::precision::tf32, wmma::row_major> bf[4];
#pragma unroll
            for (int i = 0; i < 2; i++) {
                wmma::load_matrix_sync(af[i], &as[(wm * 32 + i * 16) * AST + kk], AST);
#pragma unroll
                for (int e = 0; e < af[i].num_elements; e++)
                    af[i].x[e] = wmma::__float_to_tf32(af[i].x[e]);
            }
#pragma unroll
            for (int j = 0; j < 4; j++) {
                wmma::load_matrix_sync(bf[j], &bs[kk * 128 + wn * 64 + j * 16], 128);
#pragma unroll
                for (int e = 0; e < bf[j].num_elements; e++)
                    bf[j].x[e] = wmma::__float_to_tf32(bf[j].x[e]);
            }
#pragma unroll
            for (int i = 0; i < 2; i++)
#pragma unroll
                for (int j = 0; j < 4; j++)
                    wmma::mma_sync(acc[i][j], af[i], bf[j], acc[i][j]);
        }
        __syncthreads();
    }

    // epilogue: stage fp32 frag in smem, convert to fp16, 16B stores
#pragma unroll
    for (int i = 0; i < 2; i++)
#pragma unroll
        for (int j = 0; j < 4; j++) {
            wmma::store_matrix_sync(&stg[wid][0], acc[i][j], 16, wmma::mem_row_major);
            __syncwarp();
            int base = lane * 8;
            int r = base >> 4;          // 0..15 (lane/2)
            int c = base & 15;          // 0 or 8
            const float* sp = &stg[wid][r * 16 + c];
            __half2 h[4];
#pragma unroll
            for (int q = 0; q < 4; q++)
                h[q] = __floats2half2_rn(sp[q * 2], sp[q * 2 + 1]);
            int row0 = bRow + wm * 32 + i * 16;
            int col0 = bCol + wn * 64 + j * 16;
            *(uint4*)(C + (size_t)(row0 + r) * M + col0 + c) = *(uint4*)h;
            __syncwarp();
        }
}

// ---------------- CSR gather aggregation (warp per dst node, fp16 in) -------
// O[d] = dinv[d] * ( sum_{s in nbr(d)} dinv[s]*H[s] + dinv[d]*H[d] ) + bias
template <int NV4>   // 4-half groups per lane: C = NV4*128
__global__ void k_agg(const __half* __restrict__ H, float* __restrict__ O,
                      const float* __restrict__ bias) {
    const int C = NV4 * 128;
    int w = (blockIdx.x * blockDim.x + threadIdx.x) >> 5;
    if (w >= NN) return;
    int lane = threadIdx.x & 31;
    float di = g_dinv[w];

    float4 acc[NV4];
    const uint2* selfp = (const uint2*)(H + (size_t)w * C);
#pragma unroll
    for (int v = 0; v < NV4; v++) {
        uint2 u = selfp[lane + 32 * v];
        float2 a = __half22float2(*(__half2*)&u.x);
        float2 b = __half22float2(*(__half2*)&u.y);
        acc[v] = make_float4(a.x * di, a.y * di, b.x * di, b.y * di);
    }
    int p = g_rowptr[w], e = g_rowptr[w + 1];
    for (; p + 1 < e; p += 2) {
        int s0 = g_col[p], s1 = g_col[p + 1];
        float w0 = g_dinv[s0], w1 = g_dinv[s1];
        const uint2* h0 = (const uint2*)(H + (size_t)s0 * C);
        const uint2* h1 = (const uint2*)(H + (size_t)s1 * C);
#pragma unroll
        for (int v = 0; v < NV4; v++) {
            uint2 u0 = h0[lane + 32 * v];
            uint2 u1 = h1[lane + 32 * v];
            float2 a0 = __half22float2(*(__half2*)&u0.x);
            float2 b0 = __half22float2(*(__half2*)&u0.y);
            float2 a1 = __half22float2(*(__half2*)&u1.x);
            float2 b1 = __half22float2(*(__half2*)&u1.y);
            acc[v].x += w0 * a0.x + w1 * a1.x;
            acc[v].y += w0 * a0.y + w1 * a1.y;
            acc[v].z += w0 * b0.x + w1 * b1.x;
            acc[v].w += w0 * b0.y + w1 * b1.y;
        }
    }
    if (p < e) {
        int s = g_col[p];
        float ws = g_dinv[s];
        const uint2* hp = (const uint2*)(H + (size_t)s * C);
#pragma unroll
        for (int v = 0; v < NV4; v++) {
            uint2 u = hp[lane + 32 * v];
            float2 a = __half22float2(*(__half2*)&u.x);
            float2 b = __half22float2(*(__half2*)&u.y);
            acc[v].x += ws * a.x; acc[v].y += ws * a.y;
            acc[v].z += ws * b.x; acc[v].w += ws * b.y;
        }
    }
#pragma unroll
    for (int v = 0; v < NV4; v++) {
        int c = (lane + 32 * v) * 4;
        float4 bb = *(const float4*)(bias + c);
        float4 o = make_float4(acc[v].x * di + bb.x, acc[v].y * di + bb.y,
                               acc[v].z * di + bb.z, acc[v].w * di + bb.w);
        *(float4*)(O + (size_t)w * C + c) = o;
    }
}

// ---------------- BatchNorm (training-mode, biased var) + ReLU ----------------
__global__ void k_bnzero() {
    int c = threadIdx.x;   // 256 threads
    g_bnsum[c] = 0.0; g_bnsumsq[c] = 0.0;
}

#define BN_P 512   // row-partials per channel
__global__ void k_bnstats(const float* __restrict__ h, int C) {
    int t = blockIdx.x * blockDim.x + threadIdx.x;
    if (t >= C * BN_P) return;
    int c = t & (C - 1);
    int p = t / C;
    float s = 0.f, q = 0.f;
    for (int r = p; r < NN; r += BN_P) {
        float x = h[(size_t)r * C + c];
        s += x; q += x * x;
    }
    atomicAdd(&g_bnsum[c], (double)s);
    atomicAdd(&g_bnsumsq[c], (double)q);
}

__global__ void k_bnfin(const float* __restrict__ gamma,
                        const float* __restrict__ beta, int C) {
    int c = blockIdx.x * blockDim.x + threadIdx.x;
    if (c >= C) return;
    double m = g_bnsum[c] / (double)NN;
    double v = g_bnsumsq[c] / (double)NN - m * m;
    float sc = gamma[c] * rsqrtf((float)v + BN_EPS);
    g_bns[c] = sc;
    g_bnt[c] = beta[c] - (float)m * sc;
}

__global__ void k_bnapply(float* __restrict__ h, int C) {
    size_t i = (size_t)blockIdx.x * blockDim.x + threadIdx.x;
    if (i >= (size_t)NN * C) return;
    int c = (int)(i & (C - 1));
    float x = h[i] * g_bns[c] + g_bnt[c];
    h[i] = fmaxf(x, 0.0f);
}

// ---------------- global mean pool (sorted batch -> contiguous ranges) -------
__global__ void k_bounds(const int* __restrict__ batch) {
    int g = threadIdx.x;            // 0..NG (65 threads)
    if (g > NG) return;
    int lo = 0, hi = NN;            // lower_bound of g
    while (lo < hi) { int mid = (lo + hi) >> 1; if (batch[mid] < g) lo = mid + 1; else hi = mid; }
    g_gstart[g] = lo;
}

__global__ void k_pool(const float* __restrict__ h) {
    int b = blockIdx.x;             // 64 blocks, 256 threads
    int c = threadIdx.x;
    int st = g_gstart[b], en = g_gstart[b + 1];
    float s = 0.f;
    for (int r = st; r < en; r++) s += h[(size_t)r * 256 + c];
    g_pool[b * 256 + c] = s / fmaxf((float)(en - st), 1.0f);
}

// ---------------- FC head ----------------
__global__ void k_fc1(const float* __restrict__ Wf0, const float* __restrict__ bf0) {
    int t = blockIdx.x * blockDim.x + threadIdx.x;
    if (t >= NG * 1024) return;
    int b = t >> 10, j = t & 1023;
    float s = bf0[j];
    const float* g = g_pool + b * 256;
    for (int c = 0; c < 256; c++) s += g[c] * Wf0[c * 1024 + j];
    g_fc1[t] = fmaxf(s, 0.0f);
}

__global__ void k_fc2(const float* __restrict__ Wf1, const float* __restrict__ bf1,
                      float* __restrict__ out) {
    int t = blockIdx.x * blockDim.x + threadIdx.x;
    if (t >= NG * 128) return;
    int b = t >> 7, j = t & 127;
    float s = bf1[j];
    const float* g = g_fc1 + b * 1024;
    for (int c = 0; c < 1024; c++) s += g[c] * Wf1[c * 128 + j];
    out[t] = s;
}

// ---------------- launcher ----------------
extern "C" void kernel_launch(void* const* d_in, const int* in_sizes, int n_in,
                              void* d_out, int out_size) {
    const float* x     = (const float*)d_in[0];
    const int*   ei    = (const int*)d_in[1];
    const int*   batch = (const int*)d_in[2];
    const float* Wg0 = (const float*)d_in[3];
    const float* bg0 = (const float*)d_in[4];
    const float* gm0 = (const float*)d_in[5];
    const float* bt0 = (const float*)d_in[6];
    const float* Wg1 = (const float*)d_in[7];
    const float* bg1 = (const float*)d_in[8];
    const float* gm1 = (const float*)d_in[9];
    const float* bt1 = (const float*)d_in[10];
    const float* Wg2 = (const float*)d_in[11];
    const float* bg2 = (const float*)d_in[12];
    const float* gm2 = (const float*)d_in[13];
    const float* bt2 = (const float*)d_in[14];
    const float* Wf0 = (const float*)d_in[15];
    const float* bf0 = (const float*)d_in[16];
    const float* Wf1 = (const float*)d_in[17];
    const float* bf1 = (const float*)d_in[18];
    float* out = (float*)d_out;

    const int* src = ei;           // edge_index[0]
    const int* dst = ei + NE;      // edge_index[1]

    __half* H; cudaGetSymbolAddress((void**)&H, g_H);
    float*  A; cudaGetSymbolAddress((void**)&A, g_A);

    const int NBLK = (NN + 1023) / 1024;   // 49

    // graph structure (rebuilt each call; reused by all 3 layers)
    k_prep<<<(NN + 255) / 256, 256>>>();
    k_deg_count<<<(NE + 255) / 256, 256>>>(dst);
    k_dinv<<<(NN + 255) / 256, 256>>>();
    k_scan1<<<NBLK, 1024>>>();
    k_scan2<<<1, 32>>>(NBLK);
    k_scan3<<<NBLK, 1024>>>();
    k_csr<<<(NE + 255) / 256, 256>>>(src, dst);
    k_bounds<<<1, 96>>>(batch);

    const int gy = NNP / 128;   // 391

    // ---- layer 0: x[50000,1280] @ Wg0[1280,128]
    k_gemm_tf32<<<dim3(1, gy), 256>>>(x, Wg0, H, NN, 1280, 128);
    k_agg<1><<<(NN * 32 + 255) / 256, 256>>>(H, A, bg0);
    k_bnzero<<<1, 256>>>();
    k_bnstats<<<(128 * BN_P + 255) / 256, 256>>>(A, 128);
    k_bnfin<<<1, 128>>>(gm0, bt0, 128);
    k_bnapply<<<((size_t)NN * 128 + 255) / 256, 256>>>(A, 128);

    // ---- layer 1: A[50048,128] @ Wg1[128,256]
    k_gemm_tf32<<<dim3(2, gy), 256>>>(A, Wg1, H, NNP, 128, 256);
    k_agg<2><<<(NN * 32 + 255) / 256, 256>>>(H, A, bg1);
    k_bnzero<<<1, 256>>>();
    k_bnstats<<<(256 * BN_P + 255) / 256, 256>>>(A, 256);
    k_bnfin<<<1, 256>>>(gm1, bt1, 256);
    k_bnapply<<<((size_t)NN * 256 + 255) / 256, 256>>>(A, 256);

    // ---- layer 2: A[50048,256] @ Wg2[256,256]
    k_gemm_tf32<<<dim3(2, gy), 256>>>(A, Wg2, H, NNP, 256, 256);
    k_agg<2><<<(NN * 32 + 255) / 256, 256>>>(H, A, bg2);
    k_bnzero<<<1, 256>>>();
    k_bnstats<<<(256 * BN_P + 255) / 256, 256>>>(A, 256);
    k_bnfin<<<1, 256>>>(gm2, bt2, 256);
    k_bnapply<<<((size_t)NN * 256 + 255) / 256, 256>>>(A, 256);

    // ---- pool + FC head
    k_pool<<<NG, 256>>>(A);
    k_fc1<<<(NG * 1024 + 255) / 256, 256>>>(Wf0, bf0);
    k_fc2<<<(NG * 128 + 255) / 256, 256>>>(Wf1, bf1, out);
}

// round 8
// speedup vs baseline: 2.4598x; 1.4572x over previous
#include <cuda_runtime.h>
#include <cuda_fp16.h>
#include <mma.h>
#include <math.h>
#include <cstdint>

using namespace nvcuda;

#define NN 50000
#define NNP 50048           // 391 * 128, padded row count for GEMM tiles
#define NE 1600000
#define NG 64
#define BN_EPS 1e-5f

// ---------------- scratch (static __device__, no allocation) ----------------
__device__ float  g_deg[NN];
__device__ float  g_dinv[NN];
__device__ int    g_rowptr[NN + 1];
__device__ int    g_cursor[NN];
__device__ int    g_col[NE];
__device__ int    g_blksum[64];
__device__ int    g_blkoff[64];
__device__ int    g_gstart[NG + 1];
__device__ __half g_H[(size_t)NNP * 256];   // GEMM output (fp16, pre-aggregation)
__device__ __half g_A[(size_t)NNP * 256];   // aggregation output / layer input (fp16)
__device__ double g_bnsum[256];
__device__ double g_bnsumsq[256];
__device__ float  g_bns[256];               // BN scale
__device__ float  g_bnt[256];               // BN shift
__device__ float  g_pool[NG * 256];
__device__ float  g_fc1[NG * 1024];

// ---------------- init / degree ----------------
__global__ void k_prep() {
    int i = blockIdx.x * blockDim.x + threadIdx.x;
    if (i < NN) { g_deg[i] = 1.0f; g_cursor[i] = 0; }
}

__global__ void k_deg_count(const int* __restrict__ dst) {
    int e = blockIdx.x * blockDim.x + threadIdx.x;
    if (e < NE) atomicAdd(&g_deg[dst[e]], 1.0f);
}

__global__ void k_dinv() {
    int i = blockIdx.x * blockDim.x + threadIdx.x;
    if (i < NN) g_dinv[i] = rsqrtf(g_deg[i]);   // deg >= 1 always (self loop)
}

// ---------------- 3-phase exclusive scan of (deg-1) -> rowptr ----------------
__global__ void k_scan1() {
    __shared__ int sh[1024];
    int tid = threadIdx.x;
    int i = blockIdx.x * 1024 + tid;
    int v = (i < NN) ? ((int)g_deg[i] - 1) : 0;
    sh[tid] = v;
    __syncthreads();
    for (int off = 1; off < 1024; off <<= 1) {
        int t = (tid >= off) ? sh[tid - off] : 0;
        __syncthreads();
        sh[tid] += t;
        __syncthreads();
    }
    if (i < NN) g_rowptr[i] = sh[tid] - v;     // block-local exclusive
    if (tid == 1023) g_blksum[blockIdx.x] = sh[1023];
}
__global__ void k_scan2(int nblk) {
    if (threadIdx.x != 0) return;
    int acc = 0;
    for (int b = 0; b < nblk; b++) { g_blkoff[b] = acc; acc += g_blksum[b]; }
    g_rowptr[NN] = acc;
}
__global__ void k_scan3() {
    int i = blockIdx.x * 1024 + threadIdx.x;
    if (i < NN) g_rowptr[i] += g_blkoff[blockIdx.x];
}

__global__ void k_csr(const int* __restrict__ src, const int* __restrict__ dst) {
    int e = blockIdx.x * blockDim.x + threadIdx.x;
    if (e >= NE) return;
    int d = dst[e];
    int p = g_rowptr[d] + atomicAdd(&g_cursor[d], 1);
    g_col[p] = src[e];
}

// ---------- fp16 HMMA GEMM (m16n16k16), register-prefetch pipeline ----------
// C[NNP,M](fp16) = A[*,K] @ B[K,M](fp32 weights, converted on load).
// A_HALF=0: A is fp32 (layer 0, x).  A_HALF=1: A is fp16 (g_A).
// BM=128, BN=128, BK=32. 8 warps: wm=wid&3 (32 rows), wn=wid>>2 (64 cols).
// Rows >= NA clamp to row 0 (garbage only in never-read pad rows).
#define ASTH 40    // As row stride in halves (32 + 8 pad)
#define BSTH 136   // Bs row stride in halves (128 + 8 pad)
template <int A_HALF>
__global__ __launch_bounds__(256) void k_gemm_h(const void* __restrict__ Aptr,
                                                const float* __restrict__ B,
                                                __half* __restrict__ C,
                                                int NA, int K, int M) {
    __shared__ __half As[128 * ASTH];
    __shared__ __half Bs[32 * BSTH];
    __shared__ float  stg[8][16 * 16 + 8];
    const int bRow = blockIdx.y * 128;
    const int bCol = blockIdx.x * 128;
    const int tid = threadIdx.x;
    const int wid = tid >> 5;
    const int lane = tid & 31;
    const int wm = wid & 3;
    const int wn = wid >> 2;

    wmma::fragment<wmma::accumulator, 16, 16, 16, float> acc[2][4];
#pragma unroll
    for (int i = 0; i < 2; i++)
#pragma unroll
        for (int j = 0; j < 4; j++) wmma::fill_fragment(acc[i][j], 0.0f);

    // prefetch registers
    float4 rbf[4];           // B tile: 32x128 fp32 = 1024 float4, 4/thread
    float4 raf[4];           // A fp32: 128x32 fp32 = 1024 float4, 4/thread
    uint4  rah[2];           // A fp16: 128x32 half = 512 uint4, 2/thread

    auto ldB = [&](int t) {
        int k0 = t * 32;
#pragma unroll
        for (int l = 0; l < 4; l++) {
            int f = tid + l * 256;
            int row = f >> 5;              // 0..31
            int c4 = (f & 31) * 4;
            rbf[l] = *(const float4*)(B + (size_t)(k0 + row) * M + bCol + c4);
        }
    };
    auto stB = [&]() {
#pragma unroll
        for (int l = 0; l < 4; l++) {
            int f = tid + l * 256;
            int row = f >> 5;
            int c4 = (f & 31) * 4;
            __half2 h0 = __floats2half2_rn(rbf[l].x, rbf[l].y);
            __half2 h1 = __floats2half2_rn(rbf[l].z, rbf[l].w);
            uint2 u = { *(unsigned*)&h0, *(unsigned*)&h1 };
            *(uint2*)&Bs[row * BSTH + c4] = u;
        }
    };
    auto ldA = [&](int t) {
        int k0 = t * 32;
        if (A_HALF) {
            const __half* A = (const __half*)Aptr;
#pragma unroll
            for (int l = 0; l < 2; l++) {
                int f = tid + l * 256;
                int row = f >> 2;          // 0..127
                int u8 = (f & 3) * 8;      // half offset within row
                int gRow = bRow + row;
                if (gRow >= NA) gRow = 0;
                rah[l] = *(const uint4*)(A + (size_t)gRow * K + k0 + u8);
            }
        } else {
            const float* A = (const float*)Aptr;
#pragma unroll
            for (int l = 0; l < 4; l++) {
                int f = tid + l * 256;
                int row = f >> 3;          // 0..127 (8 float4 per row)
                int c4 = (f & 7) * 4;
                int gRow = bRow + row;
                if (gRow >= NA) gRow = 0;
                raf[l] = *(const float4*)(A + (size_t)gRow * K + k0 + c4);
            }
        }
    };
    auto stA = [&]() {
        if (A_HALF) {
#pragma unroll
            for (int l = 0; l < 2; l++) {
                int f = tid + l * 256;
                int row = f >> 2;
                int u8 = (f & 3) * 8;
                *(uint4*)&As[row * ASTH + u8] = rah[l];
            }
        } else {
#pragma unroll
            for (int l = 0; l < 4; l++) {
                int f = tid + l * 256;
                int row = f >> 3;
                int c4 = (f & 7) * 4;
                __half2 h0 = __floats2half2_rn(raf[l].x, raf[l].y);
                __half2 h1 = __floats2half2_rn(raf[l].z, raf[l].w);
                uint2 u = { *(unsigned*)&h0, *(unsigned*)&h1 };
                *(uint2*)&As[row * ASTH + c4] = u;
            }
        }
    };

    const int T = K / 32;
    ldA(0); ldB(0);

    for (int t = 0; t < T; t++) {
        __syncthreads();           // smem from previous iter fully consumed
        stA(); stB();
        __syncthreads();
        if (t + 1 < T) { ldA(t + 1); ldB(t + 1); }   // overlap LDG with MMA
#pragma unroll
        for (int ks = 0; ks < 2; ks++) {
            wmma::fragment<wmma::matrix_a, 16, 16, 16, __half, wmma::row_major> af[2];
            wmma::fragment<wmma::matrix_b, 16, 16, 16, __half, wmma::row_major> bf[4];
#pragma unroll
            for (int i = 0; i < 2; i++)
                wmma::load_matrix_sync(af[i], &As[(wm * 32 + i * 16) * ASTH + ks * 16], ASTH);
#pragma unroll
            for (int j = 0; j < 4; j++)
                wmma::load_matrix_sync(bf[j], &Bs[(ks * 16) * BSTH + wn * 64 + j * 16], BSTH);
#pragma unroll
            for (int i = 0; i < 2; i++)
#pragma unroll
                for (int j = 0; j < 4; j++)
                    wmma::mma_sync(acc[i][j], af[i], bf[j], acc[i][j]);
        }
    }

    // epilogue: stage fp32 frag in smem, convert to fp16, 16B stores
#pragma unroll
    for (int i = 0; i < 2; i++)
#pragma unroll
        for (int j = 0; j < 4; j++) {
            wmma::store_matrix_sync(&stg[wid][0], acc[i][j], 16, wmma::mem_row_major);
            __syncwarp();
            int base = lane * 8;
            int r = base >> 4;          // 0..15
            int c = base & 15;          // 0 or 8
            const float* sp = &stg[wid][r * 16 + c];
            __half2 h[4];
#pragma unroll
            for (int q = 0; q < 4; q++)
                h[q] = __floats2half2_rn(sp[q * 2], sp[q * 2 + 1]);
            int row0 = bRow + wm * 32 + i * 16;
            int col0 = bCol + wn * 64 + j * 16;
            *(uint4*)(C + (size_t)(row0 + r) * M + col0 + c) = *(uint4*)h;
            __syncwarp();
        }
}

// ---------------- CSR gather aggregation (warp per dst node, fp16 in/out) ----
// O[d] = dinv[d] * ( sum_{s in nbr(d)} dinv[s]*H[s] + dinv[d]*H[d] ) + bias
template <int NV4>   // 4-half groups per lane: C = NV4*128
__global__ void k_agg(const __half* __restrict__ H, __half* __restrict__ O,
                      const float* __restrict__ bias) {
    const int C = NV4 * 128;
    int w = (blockIdx.x * blockDim.x + threadIdx.x) >> 5;
    if (w >= NN) return;
    int lane = threadIdx.x & 31;
    float di = g_dinv[w];

    float4 acc[NV4];
    const uint2* selfp = (const uint2*)(H + (size_t)w * C);
#pragma unroll
    for (int v = 0; v < NV4; v++) {
        uint2 u = selfp[lane + 32 * v];
        float2 a = __half22float2(*(__half2*)&u.x);
        float2 b = __half22float2(*(__half2*)&u.y);
        acc[v] = make_float4(a.x * di, a.y * di, b.x * di, b.y * di);
    }
    int p = g_rowptr[w], e = g_rowptr[w + 1];
    for (; p + 1 < e; p += 2) {
        int s0 = g_col[p], s1 = g_col[p + 1];
        float w0 = g_dinv[s0], w1 = g_dinv[s1];
        const uint2* h0 = (const uint2*)(H + (size_t)s0 * C);
        const uint2* h1 = (const uint2*)(H + (size_t)s1 * C);
#pragma unroll
        for (int v = 0; v < NV4; v++) {
            uint2 u0 = h0[lane + 32 * v];
            uint2 u1 = h1[lane + 32 * v];
            float2 a0 = __half22float2(*(__half2*)&u0.x);
            float2 b0 = __half22float2(*(__half2*)&u0.y);
            float2 a1 = __half22float2(*(__half2*)&u1.x);
            float2 b1 = __half22float2(*(__half2*)&u1.y);
            acc[v].x += w0 * a0.x + w1 * a1.x;
            acc[v].y += w0 * a0.y + w1 * a1.y;
            acc[v].z += w0 * b0.x + w1 * b1.x;
            acc[v].w += w0 * b0.y + w1 * b1.y;
        }
    }
    if (p < e) {
        int s = g_col[p];
        float ws = g_dinv[s];
        const uint2* hp = (const uint2*)(H + (size_t)s * C);
#pragma unroll
        for (int v = 0; v < NV4; v++) {
            uint2 u = hp[lane + 32 * v];
            float2 a = __half22float2(*(__half2*)&u.x);
            float2 b = __half22float2(*(__half2*)&u.y);
            acc[v].x += ws * a.x; acc[v].y += ws * a.y;
            acc[v].z += ws * b.x; acc[v].w += ws * b.y;
        }
    }
#pragma unroll
    for (int v = 0; v < NV4; v++) {
        int c = (lane + 32 * v) * 4;
        float4 bb = *(const float4*)(bias + c);
        __half2 o0 = __floats2half2_rn(acc[v].x * di + bb.x, acc[v].y * di + bb.y);
        __half2 o1 = __floats2half2_rn(acc[v].z * di + bb.z, acc[v].w * di + bb.w);
        uint2 u = { *(unsigned*)&o0, *(unsigned*)&o1 };
        *(uint2*)(O + (size_t)w * C + c) = u;
    }
}

// ---------------- BatchNorm (training-mode, biased var) + ReLU ----------------
__global__ void k_bnzero() {
    int c = threadIdx.x;   // 256 threads
    g_bnsum[c] = 0.0; g_bnsumsq[c] = 0.0;
}

#define BN_P 512   // row-partials per channel
__global__ void k_bnstats(const __half* __restrict__ h, int C) {
    int t = blockIdx.x * blockDim.x + threadIdx.x;
    if (t >= C * BN_P) return;
    int c = t & (C - 1);
    int p = t / C;
    float s = 0.f, q = 0.f;
    for (int r = p; r < NN; r += BN_P) {
        float x = __half2float(h[(size_t)r * C + c]);
        s += x; q += x * x;
    }
    atomicAdd(&g_bnsum[c], (double)s);
    atomicAdd(&g_bnsumsq[c], (double)q);
}

__global__ void k_bnfin(const float* __restrict__ gamma,
                        const float* __restrict__ beta, int C) {
    int c = blockIdx.x * blockDim.x + threadIdx.x;
    if (c >= C) return;
    double m = g_bnsum[c] / (double)NN;
    double v = g_bnsumsq[c] / (double)NN - m * m;
    float sc = gamma[c] * rsqrtf((float)v + BN_EPS);
    g_bns[c] = sc;
    g_bnt[c] = beta[c] - (float)m * sc;
}

// each thread handles 8 halves (uint4)
__global__ void k_bnapply(__half* __restrict__ h, int C) {
    size_t i = (size_t)blockIdx.x * blockDim.x + threadIdx.x;
    size_t base = i * 8;
    if (base >= (size_t)NN * C) return;
    int c0 = (int)(base & (C - 1));
    uint4 u = *(uint4*)(h + base);
    __half2* hp = (__half2*)&u;
#pragma unroll
    for (int q = 0; q < 4; q++) {
        float2 f = __half22float2(hp[q]);
        int c = c0 + q * 2;
        f.x = fmaxf(f.x * g_bns[c] + g_bnt[c], 0.0f);
        f.y = fmaxf(f.y * g_bns[c + 1] + g_bnt[c + 1], 0.0f);
        hp[q] = __floats2half2_rn(f.x, f.y);
    }
    *(uint4*)(h + base) = u;
}

// ---------------- global mean pool (sorted batch -> contiguous ranges) -------
__global__ void k_bounds(const int* __restrict__ batch) {
    int g = threadIdx.x;            // 0..NG (65 threads)
    if (g > NG) return;
    int lo = 0, hi = NN;            // lower_bound of g
    while (lo < hi) { int mid = (lo + hi) >> 1; if (batch[mid] < g) lo = mid + 1; else hi = mid; }
    g_gstart[g] = lo;
}

__global__ void k_pool(const __half* __restrict__ h) {
    int b = blockIdx.x;             // 64 blocks, 256 threads
    int c = threadIdx.x;
    int st = g_gstart[b], en = g_gstart[b + 1];
    float s = 0.f;
    for (int r = st; r < en; r++) s += __half2float(h[(size_t)r * 256 + c]);
    g_pool[b * 256 + c] = s / fmaxf((float)(en - st), 1.0f);
}

// ---------------- FC head ----------------
__global__ void k_fc1(const float* __restrict__ Wf0, const float* __restrict__ bf0) {
    int t = blockIdx.x * blockDim.x + threadIdx.x;
    if (t >= NG * 1024) return;
    int b = t >> 10, j = t & 1023;
    float s = bf0[j];
    const float* g = g_pool + b * 256;
    for (int c = 0; c < 256; c++) s += g[c] * Wf0[c * 1024 + j];
    g_fc1[t] = fmaxf(s, 0.0f);
}

__global__ void k_fc2(const float* __restrict__ Wf1, const float* __restrict__ bf1,
                      float* __restrict__ out) {
    int t = blockIdx.x * blockDim.x + threadIdx.x;
    if (t >= NG * 128) return;
    int b = t >> 7, j = t & 127;
    float s = bf1[j];
    const float* g = g_fc1 + b * 1024;
    for (int c = 0; c < 1024; c++) s += g[c] * Wf1[c * 128 + j];
    out[t] = s;
}

// ---------------- launcher ----------------
extern "C" void kernel_launch(void* const* d_in, const int* in_sizes, int n_in,
                              void* d_out, int out_size) {
    const float* x     = (const float*)d_in[0];
    const int*   ei    = (const int*)d_in[1];
    const int*   batch = (const int*)d_in[2];
    const float* Wg0 = (const float*)d_in[3];
    const float* bg0 = (const float*)d_in[4];
    const float* gm0 = (const float*)d_in[5];
    const float* bt0 = (const float*)d_in[6];
    const float* Wg1 = (const float*)d_in[7];
    const float* bg1 = (const float*)d_in[8];
    const float* gm1 = (const float*)d_in[9];
    const float* bt1 = (const float*)d_in[10];
    const float* Wg2 = (const float*)d_in[11];
    const float* bg2 = (const float*)d_in[12];
    const float* gm2 = (const float*)d_in[13];
    const float* bt2 = (const float*)d_in[14];
    const float* Wf0 = (const float*)d_in[15];
    const float* bf0 = (const float*)d_in[16];
    const float* Wf1 = (const float*)d_in[17];
    const float* bf1 = (const float*)d_in[18];
    float* out = (float*)d_out;

    const int* src = ei;           // edge_index[0]
    const int* dst = ei + NE;      // edge_index[1]

    __half* H; cudaGetSymbolAddress((void**)&H, g_H);
    __half* A; cudaGetSymbolAddress((void**)&A, g_A);

    const int NBLK = (NN + 1023) / 1024;   // 49

    // graph structure (rebuilt each call; reused by all 3 layers)
    k_prep<<<(NN + 255) / 256, 256>>>();
    k_deg_count<<<(NE + 255) / 256, 256>>>(dst);
    k_dinv<<<(NN + 255) / 256, 256>>>();
    k_scan1<<<NBLK, 1024>>>();
    k_scan2<<<1, 32>>>(NBLK);
    k_scan3<<<NBLK, 1024>>>();
    k_csr<<<(NE + 255) / 256, 256>>>(src, dst);
    k_bounds<<<1, 96>>>(batch);

    const int gy = NNP / 128;   // 391

    // ---- layer 0: x[50000,1280](fp32) @ Wg0[1280,128]
    k_gemm_h<0><<<dim3(1, gy), 256>>>(x, Wg0, H, NN, 1280, 128);
    k_agg<1><<<(NN * 32 + 255) / 256, 256>>>(H, A, bg0);
    k_bnzero<<<1, 256>>>();
    k_bnstats<<<(128 * BN_P + 255) / 256, 256>>>(A, 128);
    k_bnfin<<<1, 128>>>(gm0, bt0, 128);
    k_bnapply<<<(int)(((size_t)NN * 128 / 8 + 255) / 256), 256>>>(A, 128);

    // ---- layer 1: A[50048,128](fp16) @ Wg1[128,256]
    k_gemm_h<1><<<dim3(2, gy), 256>>>(A, Wg1, H, NNP, 128, 256);
    k_agg<2><<<(NN * 32 + 255) / 256, 256>>>(H, A, bg1);
    k_bnzero<<<1, 256>>>();
    k_bnstats<<<(256 * BN_P + 255) / 256, 256>>>(A, 256);
    k_bnfin<<<1, 256>>>(gm1, bt1, 256);
    k_bnapply<<<(int)(((size_t)NN * 256 / 8 + 255) / 256), 256>>>(A, 256);

    // ---- layer 2: A[50048,256](fp16) @ Wg2[256,256]
    k_gemm_h<1><<<dim3(2, gy), 256>>>(A, Wg2, H, NNP, 256, 256);
    k_agg<2><<<(NN * 32 + 255) / 256, 256>>>(H, A, bg2);
    k_bnzero<<<1, 256>>>();
    k_bnstats<<<(256 * BN_P + 255) / 256, 256>>>(A, 256);
    k_bnfin<<<1, 256>>>(gm2, bt2, 256);
    k_bnapply<<<(int)(((size_t)NN * 256 / 8 + 255) / 256), 256>>>(A, 256);

    // ---- pool + FC head
    k_pool<<<NG, 256>>>(A);
    k_fc1<<<(NG * 1024 + 255) / 256, 256>>>(Wf0, bf0);
    k_fc2<<<(NG * 128 + 255) / 256, 256>>>(Wf1, bf1, out);
}

// round 10
// speedup vs baseline: 2.8410x; 1.1550x over previous
#include <cuda_runtime.h>
#include <cuda_fp16.h>
#include <mma.h>
#include <math.h>
#include <cstdint>

using namespace nvcuda;

#define NN 50000
#define NNP 50048           // 391 * 128, padded row count for GEMM tiles
#define NE 1600000
#define NG 64
#define BN_EPS 1e-5f

// ---------------- scratch (static __device__, no allocation) ----------------
__device__ float  g_deg[NN];
__device__ float  g_dinv[NN];
__device__ int    g_rowptr[NN + 1];
__device__ int    g_cursor[NN];
__device__ int    g_col[NE];
__device__ int    g_blksum[64];
__device__ int    g_blkoff[64];
__device__ int    g_gstart[NG + 1];
__device__ __half g_H[(size_t)NNP * 256];   // GEMM output, pre-scaled by dinv[row]
__device__ __half g_A[(size_t)NNP * 256];   // agg output (pre-BN), fp16
__device__ double g_bnsum[256];
__device__ double g_bnsumsq[256];
__device__ float  g_bns[256];               // BN scale (current layer)
__device__ float  g_bnt[256];               // BN shift (current layer)
__device__ float  g_pool[NG * 256];
__device__ float  g_fc1[NG * 1024];

// ---------------- init / degree ----------------
__global__ void k_prep() {
    int i = blockIdx.x * blockDim.x + threadIdx.x;
    if (i < NN) { g_deg[i] = 1.0f; g_cursor[i] = 0; }
}

__global__ void k_deg_count(const int* __restrict__ dst) {
    int e = blockIdx.x * blockDim.x + threadIdx.x;
    if (e < NE) atomicAdd(&g_deg[dst[e]], 1.0f);
}

__global__ void k_dinv() {
    int i = blockIdx.x * blockDim.x + threadIdx.x;
    if (i < NN) g_dinv[i] = rsqrtf(g_deg[i]);   // deg >= 1 always (self loop)
}

// ---------------- 3-phase exclusive scan of (deg-1) -> rowptr ----------------
__global__ void k_scan1() {
    __shared__ int sh[1024];
    int tid = threadIdx.x;
    int i = blockIdx.x * 1024 + tid;
    int v = (i < NN) ? ((int)g_deg[i] - 1) : 0;
    sh[tid] = v;
    __syncthreads();
    for (int off = 1; off < 1024; off <<= 1) {
        int t = (tid >= off) ? sh[tid - off] : 0;
        __syncthreads();
        sh[tid] += t;
        __syncthreads();
    }
    if (i < NN) g_rowptr[i] = sh[tid] - v;     // block-local exclusive
    if (tid == 1023) g_blksum[blockIdx.x] = sh[1023];
}
__global__ void k_scan2(int nblk) {
    if (threadIdx.x != 0) return;
    int acc = 0;
    for (int b = 0; b < nblk; b++) { g_blkoff[b] = acc; acc += g_blksum[b]; }
    g_rowptr[NN] = acc;
}
__global__ void k_scan3() {
    int i = blockIdx.x * 1024 + threadIdx.x;
    if (i < NN) g_rowptr[i] += g_blkoff[blockIdx.x];
}

__global__ void k_csr(const int* __restrict__ src, const int* __restrict__ dst) {
    int e = blockIdx.x * blockDim.x + threadIdx.x;
    if (e >= NE) return;
    int d = dst[e];
    int p = g_rowptr[d] + atomicAdd(&g_cursor[d], 1);
    g_col[p] = src[e];
}

// ---------- fp16 HMMA GEMM (m16n16k16), register-prefetch pipeline ----------
// C[NNP,M](fp16) = dinv[row] * ( bn(A[*,K]) @ B[K,M] )
// A_HALF=0: A fp32 raw (layer 0).  A_HALF=1: A fp16.
// BN_IN=1: apply y = relu(bns[c]*x + bnt[c]) to A elements on load.
// Epilogue multiplies each output row by g_dinv[row] (H' = dinv .* H).
// Rows >= NA clamp to row 0 (garbage only in never-read pad rows).
#define ASTH 40    // As row stride in halves (32 + 8 pad)
#define BSTH 136   // Bs row stride in halves (128 + 8 pad)
template <int A_HALF, int BN_IN>
__global__ __launch_bounds__(256) void k_gemm_h(const void* __restrict__ Aptr,
                                                const float* __restrict__ B,
                                                __half* __restrict__ C,
                                                int NA, int K, int M) {
    __shared__ __half As[128 * ASTH];
    __shared__ __half Bs[32 * BSTH];
    __shared__ float  stg[8][16 * 16 + 8];
    __shared__ float  bns_s[256], bnt_s[256];
    const int bRow = blockIdx.y * 128;
    const int bCol = blockIdx.x * 128;
    const int tid = threadIdx.x;
    const int wid = tid >> 5;
    const int lane = tid & 31;
    const int wm = wid & 3;
    const int wn = wid >> 2;

    if (BN_IN) {
        for (int i = tid; i < K; i += 256) { bns_s[i] = g_bns[i]; bnt_s[i] = g_bnt[i]; }
    }

    wmma::fragment<wmma::accumulator, 16, 16, 16, float> acc[2][4];
#pragma unroll
    for (int i = 0; i < 2; i++)
#pragma unroll
        for (int j = 0; j < 4; j++) wmma::fill_fragment(acc[i][j], 0.0f);

    // prefetch registers
    float4 rbf[4];           // B tile: 32x128 fp32 = 1024 float4, 4/thread
    float4 raf[4];           // A fp32: 128x32 fp32 = 1024 float4, 4/thread
    uint4  rah[2];           // A fp16: 128x32 half = 512 uint4, 2/thread

    auto ldB = [&](int t) {
        int k0 = t * 32;
#pragma unroll
        for (int l = 0; l < 4; l++) {
            int f = tid + l * 256;
            int row = f >> 5;              // 0..31
            int c4 = (f & 31) * 4;
            rbf[l] = *(const float4*)(B + (size_t)(k0 + row) * M + bCol + c4);
        }
    };
    auto stB = [&]() {
#pragma unroll
        for (int l = 0; l < 4; l++) {
            int f = tid + l * 256;
            int row = f >> 5;
            int c4 = (f & 31) * 4;
            __half2 h0 = __floats2half2_rn(rbf[l].x, rbf[l].y);
            __half2 h1 = __floats2half2_rn(rbf[l].z, rbf[l].w);
            uint2 u = { *(unsigned*)&h0, *(unsigned*)&h1 };
            *(uint2*)&Bs[row * BSTH + c4] = u;
        }
    };
    auto ldA = [&](int t) {
        int k0 = t * 32;
        if (A_HALF) {
            const __half* A = (const __half*)Aptr;
#pragma unroll
            for (int l = 0; l < 2; l++) {
                int f = tid + l * 256;
                int row = f >> 2;          // 0..127
                int u8 = (f & 3) * 8;      // half offset within row
                int gRow = bRow + row;
                if (gRow >= NA) gRow = 0;
                rah[l] = *(const uint4*)(A + (size_t)gRow * K + k0 + u8);
            }
        } else {
            const float* A = (const float*)Aptr;
#pragma unroll
            for (int l = 0; l < 4; l++) {
                int f = tid + l * 256;
                int row = f >> 3;          // 0..127 (8 float4 per row)
                int c4 = (f & 7) * 4;
                int gRow = bRow + row;
                if (gRow >= NA) gRow = 0;
                raf[l] = *(const float4*)(A + (size_t)gRow * K + k0 + c4);
            }
        }
    };
    auto stA = [&](int t) {
        if (A_HALF) {
            int k0 = t * 32;
#pragma unroll
            for (int l = 0; l < 2; l++) {
                int f = tid + l * 256;
                int row = f >> 2;
                int u8 = (f & 3) * 8;
                uint4 u = rah[l];
                if (BN_IN) {
                    int cb = k0 + u8;
                    __half2* hp = (__half2*)&u;
#pragma unroll
                    for (int q = 0; q < 4; q++) {
                        float2 fv = __half22float2(hp[q]);
                        int c = cb + q * 2;
                        fv.x = fmaxf(fv.x * bns_s[c] + bnt_s[c], 0.0f);
                        fv.y = fmaxf(fv.y * bns_s[c + 1] + bnt_s[c + 1], 0.0f);
                        hp[q] = __floats2half2_rn(fv.x, fv.y);
                    }
                }
                *(uint4*)&As[row * ASTH + u8] = u;
            }
        } else {
#pragma unroll
            for (int l = 0; l < 4; l++) {
                int f = tid + l * 256;
                int row = f >> 3;
                int c4 = (f & 7) * 4;
                __half2 h0 = __floats2half2_rn(raf[l].x, raf[l].y);
                __half2 h1 = __floats2half2_rn(raf[l].z, raf[l].w);
                uint2 u = { *(unsigned*)&h0, *(unsigned*)&h1 };
                *(uint2*)&As[row * ASTH + c4] = u;
            }
        }
    };

    const int T = K / 32;
    ldA(0); ldB(0);

    for (int t = 0; t < T; t++) {
        __syncthreads();           // smem from previous iter fully consumed
        stA(t); stB();
        __syncthreads();
        if (t + 1 < T) { ldA(t + 1); ldB(t + 1); }   // overlap LDG with MMA
#pragma unroll
        for (int ks = 0; ks < 2; ks++) {
            wmma::fragment<wmma::matrix_a, 16, 16, 16, __half, wmma::row_major> af[2];
            wmma::fragment<wmma::matrix_b, 16, 16, 16, __half, wmma::row_major> bf[4];
#pragma unroll
            for (int i = 0; i < 2; i++)
                wmma::load_matrix_sync(af[i], &As[(wm * 32 + i * 16) * ASTH + ks * 16], ASTH);
#pragma unroll
            for (int j = 0; j < 4; j++)
                wmma::load_matrix_sync(bf[j], &Bs[(ks * 16) * BSTH + wn * 64 + j * 16], BSTH);
#pragma unroll
            for (int i = 0; i < 2; i++)
#pragma unroll
                for (int j = 0; j < 4; j++)
                    wmma::mma_sync(acc[i][j], af[i], bf[j], acc[i][j]);
        }
    }

    // epilogue: stage fp32 frag, scale row by dinv, convert to fp16, 16B store
#pragma unroll
    for (int i = 0; i < 2; i++)
#pragma unroll
        for (int j = 0; j < 4; j++) {
            wmma::store_matrix_sync(&stg[wid][0], acc[i][j], 16, wmma::mem_row_major);
            __syncwarp();
            int base = lane * 8;
            int r = base >> 4;          // 0..15
            int c = base & 15;          // 0 or 8
            const float* sp = &stg[wid][r * 16 + c];
            int row0 = bRow + wm * 32 + i * 16;
            int grow = row0 + r;
            float dr = g_dinv[grow < NN ? grow : 0];
            __half2 h[4];
#pragma unroll
            for (int q = 0; q < 4; q++)
                h[q] = __floats2half2_rn(sp[q * 2] * dr, sp[q * 2 + 1] * dr);
            int col0 = bCol + wn * 64 + j * 16;
            *(uint4*)(C + (size_t)grow * M + col0 + c) = *(uint4*)h;
            __syncwarp();
        }
}

// ------- CSR gather aggregation (warp per dst node, H pre-scaled by dinv) ----
// O[d] = dinv[d] * ( H'[d] + sum_{s in nbr(d)} H'[s] ) + bias,  H' = dinv.*H
template <int NV4>   // 4-half groups per lane: C = NV4*128
__global__ void k_agg(const __half* __restrict__ H, __half* __restrict__ O,
                      const float* __restrict__ bias) {
    const int C = NV4 * 128;
    int w = (blockIdx.x * blockDim.x + threadIdx.x) >> 5;
    if (w >= NN) return;
    int lane = threadIdx.x & 31;
    float di = g_dinv[w];

    float4 acc[NV4];
    const uint2* selfp = (const uint2*)(H + (size_t)w * C);
#pragma unroll
    for (int v = 0; v < NV4; v++) {
        uint2 u = selfp[lane + 32 * v];
        float2 a = __half22float2(*(__half2*)&u.x);
        float2 b = __half22float2(*(__half2*)&u.y);
        acc[v] = make_float4(a.x, a.y, b.x, b.y);
    }
    int p = g_rowptr[w], e = g_rowptr[w + 1];
    for (; p + 1 < e; p += 2) {
        int s0 = g_col[p], s1 = g_col[p + 1];
        const uint2* h0 = (const uint2*)(H + (size_t)s0 * C);
        const uint2* h1 = (const uint2*)(H + (size_t)s1 * C);
#pragma unroll
        for (int v = 0; v < NV4; v++) {
            uint2 u0 = h0[lane + 32 * v];
            uint2 u1 = h1[lane + 32 * v];
            float2 a0 = __half22float2(*(__half2*)&u0.x);
            float2 b0 = __half22float2(*(__half2*)&u0.y);
            float2 a1 = __half22float2(*(__half2*)&u1.x);
            float2 b1 = __half22float2(*(__half2*)&u1.y);
            acc[v].x += a0.x + a1.x;
            acc[v].y += a0.y + a1.y;
            acc[v].z += b0.x + b1.x;
            acc[v].w += b0.y + b1.y;
        }
    }
    if (p < e) {
        int s = g_col[p];
        const uint2* hp = (const uint2*)(H + (size_t)s * C);
#pragma unroll
        for (int v = 0; v < NV4; v++) {
            uint2 u = hp[lane + 32 * v];
            float2 a = __half22float2(*(__half2*)&u.x);
            float2 b = __half22float2(*(__half2*)&u.y);
            acc[v].x += a.x; acc[v].y += a.y;
            acc[v].z += b.x; acc[v].w += b.y;
        }
    }
#pragma unroll
    for (int v = 0; v < NV4; v++) {
        int c = (lane + 32 * v) * 4;
        float4 bb = *(const float4*)(bias + c);
        __half2 o0 = __floats2half2_rn(acc[v].x * di + bb.x, acc[v].y * di + bb.y);
        __half2 o1 = __floats2half2_rn(acc[v].z * di + bb.z, acc[v].w * di + bb.w);
        uint2 u = { *(unsigned*)&o0, *(unsigned*)&o1 };
        *(uint2*)(O + (size_t)w * C + c) = u;
    }
}

// ---------------- BatchNorm stats (training-mode, biased var) ----------------
__global__ void k_bnzero() {
    int c = threadIdx.x;   // 256 threads
    g_bnsum[c] = 0.0; g_bnsumsq[c] = 0.0;
}

#define BN_P 512   // row-partials per channel
__global__ void k_bnstats(const __half* __restrict__ h, int C) {
    int t = blockIdx.x * blockDim.x + threadIdx.x;
    if (t >= C * BN_P) return;
    int c = t & (C - 1);
    int p = t / C;
    float s = 0.f, q = 0.f;
    for (int r = p; r < NN; r += BN_P) {
        float x = __half2float(h[(size_t)r * C + c]);
        s += x; q += x * x;
    }
    atomicAdd(&g_bnsum[c], (double)s);
    atomicAdd(&g_bnsumsq[c], (double)q);
}

__global__ void k_bnfin(const float* __restrict__ gamma,
                        const float* __restrict__ beta, int C) {
    int c = blockIdx.x * blockDim.x + threadIdx.x;
    if (c >= C) return;
    double m = g_bnsum[c] / (double)NN;
    double v = g_bnsumsq[c] / (double)NN - m * m;
    float sc = gamma[c] * rsqrtf((float)v + BN_EPS);
    g_bns[c] = sc;
    g_bnt[c] = beta[c] - (float)m * sc;
}

// ---------------- global mean pool (sorted batch -> contiguous ranges) -------
__global__ void k_bounds(const int* __restrict__ batch) {
    int g = threadIdx.x;            // 0..NG (65 threads)
    if (g > NG) return;
    int lo = 0, hi = NN;            // lower_bound of g
    while (lo < hi) { int mid = (lo + hi) >> 1; if (batch[mid] < g) lo = mid + 1; else hi = mid; }
    g_gstart[g] = lo;
}

// pool applies layer-2 BN + ReLU on the fly (A holds pre-BN values)
__global__ void k_pool(const __half* __restrict__ h) {
    int b = blockIdx.x;             // 64 blocks, 256 threads
    int c = threadIdx.x;
    int st = g_gstart[b], en = g_gstart[b + 1];
    float sc = g_bns[c], sh = g_bnt[c];
    float s = 0.f;
    for (int r = st; r < en; r++) {
        float x = __half2float(h[(size_t)r * 256 + c]);
        s += fmaxf(x * sc + sh, 0.0f);
    }
    g_pool[b * 256 + c] = s / fmaxf((float)(en - st), 1.0f);
}

// ---------------- FC head ----------------
__global__ void k_fc1(const float* __restrict__ Wf0, const float* __restrict__ bf0) {
    int t = blockIdx.x * blockDim.x + threadIdx.x;
    if (t >= NG * 1024) return;
    int b = t >> 10, j = t & 1023;
    float s = bf0[j];
    const float* g = g_pool + b * 256;
    for (int c = 0; c < 256; c++) s += g[c] * Wf0[c * 1024 + j];
    g_fc1[t] = fmaxf(s, 0.0f);
}

__global__ void k_fc2(const float* __restrict__ Wf1, const float* __restrict__ bf1,
                      float* __restrict__ out) {
    int t = blockIdx.x * blockDim.x + threadIdx.x;
    if (t >= NG * 128) return;
    int b = t >> 7, j = t & 127;
    float s = bf1[j];
    const float* g = g_fc1 + b * 1024;
    for (int c = 0; c < 1024; c++) s += g[c] * Wf1[c * 128 + j];
    out[t] = s;
}

// ---------------- launcher ----------------
extern "C" void kernel_launch(void* const* d_in, const int* in_sizes, int n_in,
                              void* d_out, int out_size) {
    const float* x     = (const float*)d_in[0];
    const int*   ei    = (const int*)d_in[1];
    const int*   batch = (const int*)d_in[2];
    const float* Wg0 = (const float*)d_in[3];
    const float* bg0 = (const float*)d_in[4];
    const float* gm0 = (const float*)d_in[5];
    const float* bt0 = (const float*)d_in[6];
    const float* Wg1 = (const float*)d_in[7];
    const float* bg1 = (const float*)d_in[8];
    const float* gm1 = (const float*)d_in[9];
    const float* bt1 = (const float*)d_in[10];
    const float* Wg2 = (const float*)d_in[11];
    const float* bg2 = (const float*)d_in[12];
    const float* gm2 = (const float*)d_in[13];
    const float* bt2 = (const float*)d_in[14];
    const float* Wf0 = (const float*)d_in[15];
    const float* bf0 = (const float*)d_in[16];
    const float* Wf1 = (const float*)d_in[17];
    const float* bf1 = (const float*)d_in[18];
    float* out = (float*)d_out;

    const int* src = ei;           // edge_index[0]
    const int* dst = ei + NE;      // edge_index[1]

    __half* H; cudaGetSymbolAddress((void**)&H, g_H);
    __half* A; cudaGetSymbolAddress((void**)&A, g_A);

    const int NBLK = (NN + 1023) / 1024;   // 49

    // graph structure (rebuilt each call; reused by all 3 layers)
    k_prep<<<(NN + 255) / 256, 256>>>();
    k_deg_count<<<(NE + 255) / 256, 256>>>(dst);
    k_dinv<<<(NN + 255) / 256, 256>>>();
    k_scan1<<<NBLK, 1024>>>();
    k_scan2<<<1, 32>>>(NBLK);
    k_scan3<<<NBLK, 1024>>>();
    k_csr<<<(NE + 255) / 256, 256>>>(src, dst);
    k_bounds<<<1, 96>>>(batch);

    const int gy = NNP / 128;   // 391

    // ---- layer 0: x[50000,1280](fp32, raw) @ Wg0[1280,128]
    k_gemm_h<0, 0><<<dim3(1, gy), 256>>>(x, Wg0, H, NN, 1280, 128);
    k_agg<1><<<(NN * 32 + 255) / 256, 256>>>(H, A, bg0);
    k_bnzero<<<1, 256>>>();
    k_bnstats<<<(128 * BN_P + 255) / 256, 256>>>(A, 128);
    k_bnfin<<<1, 128>>>(gm0, bt0, 128);

    // ---- layer 1: bn0(A)[50048,128](fp16) @ Wg1[128,256]
    k_gemm_h<1, 1><<<dim3(2, gy), 256>>>(A, Wg1, H, NNP, 128, 256);
    k_agg<2><<<(NN * 32 + 255) / 256, 256>>>(H, A, bg1);
    k_bnzero<<<1, 256>>>();
    k_bnstats<<<(256 * BN_P + 255) / 256, 256>>>(A, 256);
    k_bnfin<<<1, 256>>>(gm1, bt1, 256);

    // ---- layer 2: bn1(A)[50048,256](fp16) @ Wg2[256,256]
    k_gemm_h<1, 1><<<dim3(2, gy), 256>>>(A, Wg2, H, NNP, 256, 256);
    k_agg<2><<<(NN * 32 + 255) / 256, 256>>>(H, A, bg2);
    k_bnzero<<<1, 256>>>();
    k_bnstats<<<(256 * BN_P + 255) / 256, 256>>>(A, 256);
    k_bnfin<<<1, 256>>>(gm2, bt2, 256);

    // ---- pool (applies bn2 + relu) + FC head
    k_pool<<<NG, 256>>>(A);
    k_fc1<<<(NG * 1024 + 255) / 256, 256>>>(Wf0, bf0);
    k_fc2<<<(NG * 128 + 255) / 256, 256>>>(Wf1, bf1, out);
}

// round 12
// speedup vs baseline: 3.0022x; 1.0567x over previous
#include <cuda_runtime.h>
#include <cuda_fp16.h>
#include <mma.h>
#include <math.h>
#include <cstdint>

using namespace nvcuda;

#define NN 50000
#define NNP 50048           // 391 * 128, padded row count for GEMM tiles
#define NE 1600000
#define NG 64
#define BN_EPS 1e-5f

// ---------------- scratch (static __device__, no allocation) ----------------
__device__ float  g_deg[NN];
__device__ float  g_dinv[NN];
__device__ int    g_rowptr[NN + 1];
__device__ int    g_cursor[NN];
__device__ int    g_col[NE];
__device__ int    g_blksum[64];
__device__ int    g_blkoff[64];
__device__ int    g_gstart[NG + 1];
__device__ __half g_H[(size_t)NNP * 256];   // GEMM output / layer-1 Xagg
__device__ __half g_A[(size_t)NNP * 256];   // conv output (pre-BN), fp16
__device__ double g_bnsum[256];
__device__ double g_bnsumsq[256];
__device__ __align__(16) float g_bns[256];  // BN scale (current layer)
__device__ __align__(16) float g_bnt[256];  // BN shift (current layer)
__device__ float  g_pool[NG * 256];
__device__ float  g_fc1[NG * 1024];

// ---------------- init / degree ----------------
__global__ void k_prep() {
    int i = blockIdx.x * blockDim.x + threadIdx.x;
    if (i < NN) { g_deg[i] = 1.0f; g_cursor[i] = 0; }
}

__global__ void k_deg_count(const int* __restrict__ dst) {
    int e = blockIdx.x * blockDim.x + threadIdx.x;
    if (e < NE) atomicAdd(&g_deg[dst[e]], 1.0f);
}

__global__ void k_dinv() {
    int i = blockIdx.x * blockDim.x + threadIdx.x;
    if (i < NN) g_dinv[i] = rsqrtf(g_deg[i]);   // deg >= 1 always (self loop)
}

// ---------------- 3-phase exclusive scan of (deg-1) -> rowptr ----------------
__global__ void k_scan1() {
    __shared__ int sh[1024];
    int tid = threadIdx.x;
    int i = blockIdx.x * 1024 + tid;
    int v = (i < NN) ? ((int)g_deg[i] - 1) : 0;
    sh[tid] = v;
    __syncthreads();
    for (int off = 1; off < 1024; off <<= 1) {
        int t = (tid >= off) ? sh[tid - off] : 0;
        __syncthreads();
        sh[tid] += t;
        __syncthreads();
    }
    if (i < NN) g_rowptr[i] = sh[tid] - v;     // block-local exclusive
    if (tid == 1023) g_blksum[blockIdx.x] = sh[1023];
}
__global__ void k_scan2(int nblk) {
    if (threadIdx.x != 0) return;
    int acc = 0;
    for (int b = 0; b < nblk; b++) { g_blkoff[b] = acc; acc += g_blksum[b]; }
    g_rowptr[NN] = acc;
}
__global__ void k_scan3() {
    int i = blockIdx.x * 1024 + threadIdx.x;
    if (i < NN) g_rowptr[i] += g_blkoff[blockIdx.x];
}

__global__ void k_csr(const int* __restrict__ src, const int* __restrict__ dst) {
    int e = blockIdx.x * blockDim.x + threadIdx.x;
    if (e >= NE) return;
    int d = dst[e];
    int p = g_rowptr[d] + atomicAdd(&g_cursor[d], 1);
    g_col[p] = src[e];
}

// ---- fp16 HMMA GEMM (m16n16k16), double-buffered smem + reg prefetch ------
// C[NNP,M](fp16) = epi( bn(A[*,K]) @ B[K,M] )
// A_HALF=0: A fp32 raw.  A_HALF=1: A fp16.
// BN_IN=1: apply y = relu(bns[c]*x + bnt[c]) to A elements on load.
// ADD_BIAS=1: epilogue adds Bias[col]; else epilogue scales row by g_dinv[row].
// Rows >= NA clamp to row 0 (garbage only in never-read pad rows).
#define ASTH 40    // As row stride in halves (32 + 8 pad)
#define BSTH 136   // Bs row stride in halves (128 + 8 pad)
template <int A_HALF, int BN_IN, int ADD_BIAS>
__global__ __launch_bounds__(256) void k_gemm_h(const void* __restrict__ Aptr,
                                                const float* __restrict__ B,
                                                const float* __restrict__ Bias,
                                                __half* __restrict__ C,
                                                int NA, int K, int M) {
    __shared__ __half As[2][128 * ASTH];
    __shared__ __half Bs[2][32 * BSTH];
    __shared__ float  stg[8][16 * 16 + 8];
    __shared__ float  bns_s[256], bnt_s[256];
    const int bRow = blockIdx.y * 128;
    const int bCol = blockIdx.x * 128;
    const int tid = threadIdx.x;
    const int wid = tid >> 5;
    const int lane = tid & 31;
    const int wm = wid & 3;
    const int wn = wid >> 2;

    if (BN_IN) {
        for (int i = tid; i < K; i += 256) { bns_s[i] = g_bns[i]; bnt_s[i] = g_bnt[i]; }
        __syncthreads();   // bns_s/bnt_s visible to all threads before stA(0,0)
    }

    wmma::fragment<wmma::accumulator, 16, 16, 16, float> acc[2][4];
#pragma unroll
    for (int i = 0; i < 2; i++)
#pragma unroll
        for (int j = 0; j < 4; j++) wmma::fill_fragment(acc[i][j], 0.0f);

    // prefetch registers
    float4 rbf[4];           // B tile: 32x128 fp32 = 1024 float4, 4/thread
    float4 raf[4];           // A fp32: 128x32 fp32 = 1024 float4, 4/thread
    uint4  rah[2];           // A fp16: 128x32 half = 512 uint4, 2/thread

    auto ldB = [&](int t) {
        int k0 = t * 32;
#pragma unroll
        for (int l = 0; l < 4; l++) {
            int f = tid + l * 256;
            int row = f >> 5;              // 0..31
            int c4 = (f & 31) * 4;
            rbf[l] = *(const float4*)(B + (size_t)(k0 + row) * M + bCol + c4);
        }
    };
    auto stB = [&](int stage) {
#pragma unroll
        for (int l = 0; l < 4; l++) {
            int f = tid + l * 256;
            int row = f >> 5;
            int c4 = (f & 31) * 4;
            __half2 h0 = __floats2half2_rn(rbf[l].x, rbf[l].y);
            __half2 h1 = __floats2half2_rn(rbf[l].z, rbf[l].w);
            uint2 u = { *(unsigned*)&h0, *(unsigned*)&h1 };
            *(uint2*)&Bs[stage][row * BSTH + c4] = u;
        }
    };
    auto ldA = [&](int t) {
        int k0 = t * 32;
        if (A_HALF) {
            const __half* A = (const __half*)Aptr;
#pragma unroll
            for (int l = 0; l < 2; l++) {
                int f = tid + l * 256;
                int row = f >> 2;          // 0..127
                int u8 = (f & 3) * 8;      // half offset within row
                int gRow = bRow + row;
                if (gRow >= NA) gRow = 0;
                rah[l] = *(const uint4*)(A + (size_t)gRow * K + k0 + u8);
            }
        } else {
            const float* A = (const float*)Aptr;
#pragma unroll
            for (int l = 0; l < 4; l++) {
                int f = tid + l * 256;
                int row = f >> 3;          // 0..127 (8 float4 per row)
                int c4 = (f & 7) * 4;
                int gRow = bRow + row;
                if (gRow >= NA) gRow = 0;
                raf[l] = *(const float4*)(A + (size_t)gRow * K + k0 + c4);
            }
        }
    };
    auto stA = [&](int t, int stage) {
        if (A_HALF) {
            int k0 = t * 32;
#pragma unroll
            for (int l = 0; l < 2; l++) {
                int f = tid + l * 256;
                int row = f >> 2;
                int u8 = (f & 3) * 8;
                uint4 u = rah[l];
                if (BN_IN) {
                    int cb = k0 + u8;
                    __half2* hp = (__half2*)&u;
#pragma unroll
                    for (int q = 0; q < 4; q++) {
                        float2 fv = __half22float2(hp[q]);
                        int c = cb + q * 2;
                        fv.x = fmaxf(fv.x * bns_s[c] + bnt_s[c], 0.0f);
                        fv.y = fmaxf(fv.y * bns_s[c + 1] + bnt_s[c + 1], 0.0f);
                        hp[q] = __floats2half2_rn(fv.x, fv.y);
                    }
                }
                *(uint4*)&As[stage][row * ASTH + u8] = u;
            }
        } else {
#pragma unroll
            for (int l = 0; l < 4; l++) {
                int f = tid + l * 256;
                int row = f >> 3;
                int c4 = (f & 7) * 4;
                __half2 h0 = __floats2half2_rn(raf[l].x, raf[l].y);
                __half2 h1 = __floats2half2_rn(raf[l].z, raf[l].w);
                uint2 u = { *(unsigned*)&h0, *(unsigned*)&h1 };
                *(uint2*)&As[stage][row * ASTH + c4] = u;
            }
        }
    };

    const int T = K / 32;
    ldA(0); ldB(0);
    stA(0, 0); stB(0);
    if (T > 1) { ldA(1); ldB(1); }
    __syncthreads();

    for (int t = 0; t < T; t++) {
        const __half* as = As[t & 1];
        const __half* bs = Bs[t & 1];
#pragma unroll
        for (int ks = 0; ks < 2; ks++) {
            wmma::fragment<wmma::matrix_a, 16, 16, 16, __half, wmma::row_major> af[2];
            wmma::fragment<wmma::matrix_b, 16, 16, 16, __half, wmma::row_major> bf[4];
#pragma unroll
            for (int i = 0; i < 2; i++)
                wmma::load_matrix_sync(af[i], &as[(wm * 32 + i * 16) * ASTH + ks * 16], ASTH);
#pragma unroll
            for (int j = 0; j < 4; j++)
                wmma::load_matrix_sync(bf[j], &bs[(ks * 16) * BSTH + wn * 64 + j * 16], BSTH);
#pragma unroll
            for (int i = 0; i < 2; i++)
#pragma unroll
                for (int j = 0; j < 4; j++)
                    wmma::mma_sync(acc[i][j], af[i], bf[j], acc[i][j]);
        }
        if (t + 1 < T) {
            stA(t + 1, (t + 1) & 1); stB((t + 1) & 1);   // other buffer: no race
            if (t + 2 < T) { ldA(t + 2); ldB(t + 2); }
            __syncthreads();
        }
    }

    // epilogue: stage fp32 frag, apply dinv-scale or +bias, fp16 16B stores
#pragma unroll
    for (int i = 0; i < 2; i++)
#pragma unroll
        for (int j = 0; j < 4; j++) {
            wmma::store_matrix_sync(&stg[wid][0], acc[i][j], 16, wmma::mem_row_major);
            __syncwarp();
            int base = lane * 8;
            int r = base >> 4;          // 0..15
            int c = base & 15;          // 0 or 8
            const float* sp = &stg[wid][r * 16 + c];
            int row0 = bRow + wm * 32 + i * 16;
            int grow = row0 + r;
            int col0 = bCol + wn * 64 + j * 16;
            __half2 h[4];
            if (ADD_BIAS) {
#pragma unroll
                for (int q = 0; q < 4; q++) {
                    float b0 = Bias[col0 + c + q * 2];
                    float b1 = Bias[col0 + c + q * 2 + 1];
                    h[q] = __floats2half2_rn(sp[q * 2] + b0, sp[q * 2 + 1] + b1);
                }
            } else {
                float dr = g_dinv[grow < NN ? grow : 0];
#pragma unroll
                for (int q = 0; q < 4; q++)
                    h[q] = __floats2half2_rn(sp[q * 2] * dr, sp[q * 2 + 1] * dr);
            }
            *(uint4*)(C + (size_t)grow * M + col0 + c) = *(uint4*)h;
            __syncwarp();
        }
}

// ------- CSR gather aggregation (warp per dst node, H pre-scaled by dinv) ----
// O[d] = dinv[d] * ( H'[d] + sum_{s in nbr(d)} H'[s] ) + bias,  H' = dinv.*H
template <int NV4>   // 4-half groups per lane: C = NV4*128
__global__ void k_agg(const __half* __restrict__ H, __half* __restrict__ O,
                      const float* __restrict__ bias) {
    const int C = NV4 * 128;
    int w = (blockIdx.x * blockDim.x + threadIdx.x) >> 5;
    if (w >= NN) return;
    int lane = threadIdx.x & 31;
    float di = g_dinv[w];

    float4 acc[NV4];
    const uint2* selfp = (const uint2*)(H + (size_t)w * C);
#pragma unroll
    for (int v = 0; v < NV4; v++) {
        uint2 u = selfp[lane + 32 * v];
        float2 a = __half22float2(*(__half2*)&u.x);
        float2 b = __half22float2(*(__half2*)&u.y);
        acc[v] = make_float4(a.x, a.y, b.x, b.y);
    }
    int p = g_rowptr[w], e = g_rowptr[w + 1];
    for (; p + 1 < e; p += 2) {
        int s0 = g_col[p], s1 = g_col[p + 1];
        const uint2* h0 = (const uint2*)(H + (size_t)s0 * C);
        const uint2* h1 = (const uint2*)(H + (size_t)s1 * C);
#pragma unroll
        for (int v = 0; v < NV4; v++) {
            uint2 u0 = h0[lane + 32 * v];
            uint2 u1 = h1[lane + 32 * v];
            float2 a0 = __half22float2(*(__half2*)&u0.x);
            float2 b0 = __half22float2(*(__half2*)&u0.y);
            float2 a1 = __half22float2(*(__half2*)&u1.x);
            float2 b1 = __half22float2(*(__half2*)&u1.y);
            acc[v].x += a0.x + a1.x;
            acc[v].y += a0.y + a1.y;
            acc[v].z += b0.x + b1.x;
            acc[v].w += b0.y + b1.y;
        }
    }
    if (p < e) {
        int s = g_col[p];
        const uint2* hp = (const uint2*)(H + (size_t)s * C);
#pragma unroll
        for (int v = 0; v < NV4; v++) {
            uint2 u = hp[lane + 32 * v];
            float2 a = __half22float2(*(__half2*)&u.x);
            float2 b = __half22float2(*(__half2*)&u.y);
            acc[v].x += a.x; acc[v].y += a.y;
            acc[v].z += b.x; acc[v].w += b.y;
        }
    }
#pragma unroll
    for (int v = 0; v < NV4; v++) {
        int c = (lane + 32 * v) * 4;
        float4 bb = *(const float4*)(bias + c);
        __half2 o0 = __floats2half2_rn(acc[v].x * di + bb.x, acc[v].y * di + bb.y);
        __half2 o1 = __floats2half2_rn(acc[v].z * di + bb.z, acc[v].w * di + bb.w);
        uint2 u = { *(unsigned*)&o0, *(unsigned*)&o1 };
        *(uint2*)(O + (size_t)w * C + c) = u;
    }
}

// ---- layer-1 aggregate-before-transform: X[d] = dinv_d*(Σ dinv_s*f(A[s]) + dinv_d*f(A[d]))
// f(x) = relu(bns[c]*x + bnt[c]).  C = 128 (one uint2 per lane).
__device__ __forceinline__ float4 bnrelu4(uint2 u, float4 sc, float4 tc) {
    float2 a = __half22float2(*(__half2*)&u.x);
    float2 b = __half22float2(*(__half2*)&u.y);
    float4 r;
    r.x = fmaxf(a.x * sc.x + tc.x, 0.0f);
    r.y = fmaxf(a.y * sc.y + tc.y, 0.0f);
    r.z = fmaxf(b.x * sc.z + tc.z, 0.0f);
    r.w = fmaxf(b.y * sc.w + tc.w, 0.0f);
    return r;
}
__global__ void k_aggx(const __half* __restrict__ A0, __half* __restrict__ X) {
    int w = (blockIdx.x * blockDim.x + threadIdx.x) >> 5;
    if (w >= NN) return;
    int lane = threadIdx.x & 31;
    int c4 = lane * 4;
    float di = g_dinv[w];
    float4 sc = *(const float4*)&g_bns[c4];
    float4 tc = *(const float4*)&g_bnt[c4];

    uint2 us = *(const uint2*)(A0 + (size_t)w * 128 + c4);
    float4 fs = bnrelu4(us, sc, tc);
    float4 acc = make_float4(fs.x * di, fs.y * di, fs.z * di, fs.w * di);

    int p = g_rowptr[w], e = g_rowptr[w + 1];
    for (; p + 1 < e; p += 2) {
        int s0 = g_col[p], s1 = g_col[p + 1];
        float d0 = g_dinv[s0], d1 = g_dinv[s1];
        uint2 u0 = *(const uint2*)(A0 + (size_t)s0 * 128 + c4);
        uint2 u1 = *(const uint2*)(A0 + (size_t)s1 * 128 + c4);
        float4 f0 = bnrelu4(u0, sc, tc);
        float4 f1 = bnrelu4(u1, sc, tc);
        acc.x += d0 * f0.x + d1 * f1.x;
        acc.y += d0 * f0.y + d1 * f1.y;
        acc.z += d0 * f0.z + d1 * f1.z;
        acc.w += d0 * f0.w + d1 * f1.w;
    }
    if (p < e) {
        int s = g_col[p];
        float ds = g_dinv[s];
        uint2 u = *(const uint2*)(A0 + (size_t)s * 128 + c4);
        float4 f = bnrelu4(u, sc, tc);
        acc.x += ds * f.x; acc.y += ds * f.y;
        acc.z += ds * f.z; acc.w += ds * f.w;
    }
    __half2 o0 = __floats2half2_rn(acc.x * di, acc.y * di);
    __half2 o1 = __floats2half2_rn(acc.z * di, acc.w * di);
    uint2 u = { *(unsigned*)&o0, *(unsigned*)&o1 };
    *(uint2*)(X + (size_t)w * 128 + c4) = u;
}

// ---------------- BatchNorm stats (training-mode, biased var) ----------------
__global__ void k_bnzero() {
    int c = threadIdx.x;   // 256 threads
    g_bnsum[c] = 0.0; g_bnsumsq[c] = 0.0;
}

#define BN_P 512   // row-partials per channel
__global__ void k_bnstats(const __half* __restrict__ h, int C) {
    int t = blockIdx.x * blockDim.x + threadIdx.x;
    if (t >= C * BN_P) return;
    int c = t & (C - 1);
    int p = t / C;
    float s = 0.f, q = 0.f;
    for (int r = p; r < NN; r += BN_P) {
        float x = __half2float(h[(size_t)r * C + c]);
        s += x; q += x * x;
    }
    atomicAdd(&g_bnsum[c], (double)s);
    atomicAdd(&g_bnsumsq[c], (double)q);
}

__global__ void k_bnfin(const float* __restrict__ gamma,
                        const float* __restrict__ beta, int C) {
    int c = blockIdx.x * blockDim.x + threadIdx.x;
    if (c >= C) return;
    double m = g_bnsum[c] / (double)NN;
    double v = g_bnsumsq[c] / (double)NN - m * m;
    float sc = gamma[c] * rsqrtf((float)v + BN_EPS);
    g_bns[c] = sc;
    g_bnt[c] = beta[c] - (float)m * sc;
}

// ---------------- global mean pool (sorted batch -> contiguous ranges) -------
__global__ void k_bounds(const int* __restrict__ batch) {
    int g = threadIdx.x;            // 0..NG (65 threads)
    if (g > NG) return;
    int lo = 0, hi = NN;            // lower_bound of g
    while (lo < hi) { int mid = (lo + hi) >> 1; if (batch[mid] < g) lo = mid + 1; else hi = mid; }
    g_gstart[g] = lo;
}

// pool applies layer-2 BN + ReLU on the fly (A holds pre-BN values)
__global__ void k_pool(const __half* __restrict__ h) {
    int b = blockIdx.x;             // 64 blocks, 256 threads
    int c = threadIdx.x;
    int st = g_gstart[b], en = g_gstart[b + 1];
    float sc = g_bns[c], sh = g_bnt[c];
    float s = 0.f;
    for (int r = st; r < en; r++) {
        float x = __half2float(h[(size_t)r * 256 + c]);
        s += fmaxf(x * sc + sh, 0.0f);
    }
    g_pool[b * 256 + c] = s / fmaxf((float)(en - st), 1.0f);
}

// ---------------- FC head ----------------
__global__ void k_fc1(const float* __restrict__ Wf0, const float* __restrict__ bf0) {
    int t = blockIdx.x * blockDim.x + threadIdx.x;
    if (t >= NG * 1024) return;
    int b = t >> 10, j = t & 1023;
    float s = bf0[j];
    const float* g = g_pool + b * 256;
    for (int c = 0; c < 256; c++) s += g[c] * Wf0[c * 1024 + j];
    g_fc1[t] = fmaxf(s, 0.0f);
}

__global__ void k_fc2(const float* __restrict__ Wf1, const float* __restrict__ bf1,
                      float* __restrict__ out) {
    int t = blockIdx.x * blockDim.x + threadIdx.x;
    if (t >= NG * 128) return;
    int b = t >> 7, j = t & 127;
    float s = bf1[j];
    const float* g = g_fc1 + b * 1024;
    for (int c = 0; c < 1024; c++) s += g[c] * Wf1[c * 128 + j];
    out[t] = s;
}

// ---------------- launcher ----------------
extern "C" void kernel_launch(void* const* d_in, const int* in_sizes, int n_in,
                              void* d_out, int out_size) {
    const float* x     = (const float*)d_in[0];
    const int*   ei    = (const int*)d_in[1];
    const int*   batch = (const int*)d_in[2];
    const float* Wg0 = (const float*)d_in[3];
    const float* bg0 = (const float*)d_in[4];
    const float* gm0 = (const float*)d_in[5];
    const float* bt0 = (const float*)d_in[6];
    const float* Wg1 = (const float*)d_in[7];
    const float* bg1 = (const float*)d_in[8];
    const float* gm1 = (const float*)d_in[9];
    const float* bt1 = (const float*)d_in[10];
    const float* Wg2 = (const float*)d_in[11];
    const float* bg2 = (const float*)d_in[12];
    const float* gm2 = (const float*)d_in[13];
    const float* bt2 = (const float*)d_in[14];
    const float* Wf0 = (const float*)d_in[15];
    const float* bf0 = (const float*)d_in[16];
    const float* Wf1 = (const float*)d_in[17];
    const float* bf1 = (const float*)d_in[18];
    float* out = (float*)d_out;

    const int* src = ei;           // edge_index[0]
    const int* dst = ei + NE;      // edge_index[1]

    __half* H; cudaGetSymbolAddress((void**)&H, g_H);
    __half* A; cudaGetSymbolAddress((void**)&A, g_A);

    const int NBLK = (NN + 1023) / 1024;   // 49

    // graph structure (rebuilt each call; reused by all 3 layers)
    k_prep<<<(NN + 255) / 256, 256>>>();
    k_deg_count<<<(NE + 255) / 256, 256>>>(dst);
    k_dinv<<<(NN + 255) / 256, 256>>>();
    k_scan1<<<NBLK, 1024>>>();
    k_scan2<<<1, 32>>>(NBLK);
    k_scan3<<<NBLK, 1024>>>();
    k_csr<<<(NE + 255) / 256, 256>>>(src, dst);
    k_bounds<<<1, 96>>>(batch);

    const int gy = NNP / 128;   // 391

    // ---- layer 0 (transform-first): H = dinv .* (x @ Wg0); A0 = agg(H) + b0
    k_gemm_h<0, 0, 0><<<dim3(1, gy), 256>>>(x, Wg0, nullptr, H, NN, 1280, 128);
    k_agg<1><<<(NN * 32 + 255) / 256, 256>>>(H, A, bg0);
    k_bnzero<<<1, 256>>>();
    k_bnstats<<<(128 * BN_P + 255) / 256, 256>>>(A, 128);
    k_bnfin<<<1, 128>>>(gm0, bt0, 128);

    // ---- layer 1 (aggregate-first): X = agg(relu(bn0(A0))); A1 = X @ Wg1 + b1
    k_aggx<<<(NN * 32 + 255) / 256, 256>>>(A, H);
    k_gemm_h<1, 0, 1><<<dim3(2, gy), 256>>>(H, Wg1, bg1, A, NN, 128, 256);
    k_bnzero<<<1, 256>>>();
    k_bnstats<<<(256 * BN_P + 255) / 256, 256>>>(A, 256);
    k_bnfin<<<1, 256>>>(gm1, bt1, 256);

    // ---- layer 2 (transform-first): H = dinv .* (relu(bn1(A1)) @ Wg2); A2 = agg(H)+b2
    k_gemm_h<1, 1, 0><<<dim3(2, gy), 256>>>(A, Wg2, nullptr, H, NNP, 256, 256);
    k_agg<2><<<(NN * 32 + 255) / 256, 256>>>(H, A, bg2);
    k_bnzero<<<1, 256>>>();
    k_bnstats<<<(256 * BN_P + 255) / 256, 256>>>(A, 256);
    k_bnfin<<<1, 256>>>(gm2, bt2, 256);

    // ---- pool (applies bn2 + relu) + FC head
    k_pool<<<NG, 256>>>(A);
    k_fc1<<<(NG * 1024 + 255) / 256, 256>>>(Wf0, bf0);
    k_fc2<<<(NG * 128 + 255) / 256, 256>>>(Wf1, bf1, out);
}

// round 13
// speedup vs baseline: 3.0919x; 1.0299x over previous
#include <cuda_runtime.h>
#include <cuda_fp16.h>
#include <mma.h>
#include <math.h>
#include <cstdint>

using namespace nvcuda;

#define NN 50000
#define NNP 50048           // 391 * 128, padded row count for GEMM tiles
#define NE 1600000
#define NG 64
#define BN_EPS 1e-5f

// ---------------- scratch (static __device__, no allocation) ----------------
__device__ float  g_deg[NN];
__device__ float  g_dinv[NN];
__device__ int    g_rowptr[NN + 1];
__device__ int    g_cursor[NN];
__device__ int    g_col[NE];
__device__ int    g_blksum[64];
__device__ int    g_blkoff[64];
__device__ int    g_gstart[NG + 1];
__device__ __half g_H[(size_t)NNP * 256];   // GEMM output / layer-1 Xagg
__device__ __half g_A[(size_t)NNP * 256];   // conv output (pre-BN), fp16
__device__ double g_bnsum[256];
__device__ double g_bnsumsq[256];
__device__ __align__(16) float g_bns[256];  // BN scale (current layer)
__device__ __align__(16) float g_bnt[256];  // BN shift (current layer)
__device__ float  g_pool[NG * 256];
__device__ float  g_fc1[NG * 1024];

// ---------------- init / degree ----------------
__global__ void k_prep() {
    int i = blockIdx.x * blockDim.x + threadIdx.x;
    if (i < NN) g_deg[i] = 1.0f;
}

__global__ void k_deg_count(const int* __restrict__ dst) {
    int e = blockIdx.x * blockDim.x + threadIdx.x;
    if (e < NE) atomicAdd(&g_deg[dst[e]], 1.0f);
}

__global__ void k_dinv() {
    int i = blockIdx.x * blockDim.x + threadIdx.x;
    if (i < NN) g_dinv[i] = rsqrtf(g_deg[i]);   // deg >= 1 always (self loop)
}

// ---------------- 3-phase exclusive scan of (deg-1) -> rowptr ----------------
__global__ void k_scan1() {
    __shared__ int sh[1024];
    int tid = threadIdx.x;
    int i = blockIdx.x * 1024 + tid;
    int v = (i < NN) ? ((int)g_deg[i] - 1) : 0;
    sh[tid] = v;
    __syncthreads();
    for (int off = 1; off < 1024; off <<= 1) {
        int t = (tid >= off) ? sh[tid - off] : 0;
        __syncthreads();
        sh[tid] += t;
        __syncthreads();
    }
    if (i < NN) g_rowptr[i] = sh[tid] - v;     // block-local exclusive
    if (tid == 1023) g_blksum[blockIdx.x] = sh[1023];
}
__global__ void k_scan2(int nblk) {
    if (threadIdx.x != 0) return;
    int acc = 0;
    for (int b = 0; b < nblk; b++) { g_blkoff[b] = acc; acc += g_blksum[b]; }
    g_rowptr[NN] = acc;
}
__global__ void k_scan3() {
    int i = blockIdx.x * 1024 + threadIdx.x;
    if (i < NN) {
        int r = g_rowptr[i] + g_blkoff[blockIdx.x];
        g_rowptr[i] = r;
        g_cursor[i] = r;           // csr atomics return slot directly
    }
}

__global__ void k_csr(const int* __restrict__ src, const int* __restrict__ dst) {
    int e = blockIdx.x * blockDim.x + threadIdx.x;
    if (e >= NE) return;
    int p = atomicAdd(&g_cursor[dst[e]], 1);
    g_col[p] = src[e];
}

// ---- fp16 HMMA GEMM (m16n16k16), double-buffered smem + reg prefetch ------
// C[NNP,M](fp16) = epi( bn(A[*,K]) @ B[K,M] )
// A_HALF=0: A fp32 raw.  A_HALF=1: A fp16.
// BN_IN=1: apply y = relu(bns[c]*x + bnt[c]) to A elements on load.
// ADD_BIAS=1: epilogue adds Bias[col]; else epilogue scales row by g_dinv[row].
// Rows >= NA clamp to row 0 (garbage only in never-read pad rows).
#define ASTH 40    // As row stride in halves (32 + 8 pad)
#define BSTH 136   // Bs row stride in halves (128 + 8 pad)
template <int A_HALF, int BN_IN, int ADD_BIAS>
__global__ __launch_bounds__(256) void k_gemm_h(const void* __restrict__ Aptr,
                                                const float* __restrict__ B,
                                                const float* __restrict__ Bias,
                                                __half* __restrict__ C,
                                                int NA, int K, int M) {
    __shared__ __half As[2][128 * ASTH];
    __shared__ __half Bs[2][32 * BSTH];
    __shared__ float  stg[8][16 * 16 + 8];
    __shared__ float  bns_s[256], bnt_s[256];
    const int bRow = blockIdx.y * 128;
    const int bCol = blockIdx.x * 128;
    const int tid = threadIdx.x;
    const int wid = tid >> 5;
    const int lane = tid & 31;
    const int wm = wid & 3;
    const int wn = wid >> 2;

    if (BN_IN) {
        for (int i = tid; i < K; i += 256) { bns_s[i] = g_bns[i]; bnt_s[i] = g_bnt[i]; }
        __syncthreads();   // bns_s/bnt_s visible to all threads before stA(0,0)
    }

    wmma::fragment<wmma::accumulator, 16, 16, 16, float> acc[2][4];
#pragma unroll
    for (int i = 0; i < 2; i++)
#pragma unroll
        for (int j = 0; j < 4; j++) wmma::fill_fragment(acc[i][j], 0.0f);

    // prefetch registers
    float4 rbf[4];           // B tile: 32x128 fp32 = 1024 float4, 4/thread
    float4 raf[4];           // A fp32: 128x32 fp32 = 1024 float4, 4/thread
    uint4  rah[2];           // A fp16: 128x32 half = 512 uint4, 2/thread

    auto ldB = [&](int t) {
        int k0 = t * 32;
#pragma unroll
        for (int l = 0; l < 4; l++) {
            int f = tid + l * 256;
            int row = f >> 5;              // 0..31
            int c4 = (f & 31) * 4;
            rbf[l] = *(const float4*)(B + (size_t)(k0 + row) * M + bCol + c4);
        }
    };
    auto stB = [&](int stage) {
#pragma unroll
        for (int l = 0; l < 4; l++) {
            int f = tid + l * 256;
            int row = f >> 5;
            int c4 = (f & 31) * 4;
            __half2 h0 = __floats2half2_rn(rbf[l].x, rbf[l].y);
            __half2 h1 = __floats2half2_rn(rbf[l].z, rbf[l].w);
            uint2 u = { *(unsigned*)&h0, *(unsigned*)&h1 };
            *(uint2*)&Bs[stage][row * BSTH + c4] = u;
        }
    };
    auto ldA = [&](int t) {
        int k0 = t * 32;
        if (A_HALF) {
            const __half* A = (const __half*)Aptr;
#pragma unroll
            for (int l = 0; l < 2; l++) {
                int f = tid + l * 256;
                int row = f >> 2;          // 0..127
                int u8 = (f & 3) * 8;      // half offset within row
                int gRow = bRow + row;
                if (gRow >= NA) gRow = 0;
                rah[l] = *(const uint4*)(A + (size_t)gRow * K + k0 + u8);
            }
        } else {
            const float* A = (const float*)Aptr;
#pragma unroll
            for (int l = 0; l < 4; l++) {
                int f = tid + l * 256;
                int row = f >> 3;          // 0..127 (8 float4 per row)
                int c4 = (f & 7) * 4;
                int gRow = bRow + row;
                if (gRow >= NA) gRow = 0;
                raf[l] = *(const float4*)(A + (size_t)gRow * K + k0 + c4);
            }
        }
    };
    auto stA = [&](int t, int stage) {
        if (A_HALF) {
            int k0 = t * 32;
#pragma unroll
            for (int l = 0; l < 2; l++) {
                int f = tid + l * 256;
                int row = f >> 2;
                int u8 = (f & 3) * 8;
                uint4 u = rah[l];
                if (BN_IN) {
                    int cb = k0 + u8;
                    __half2* hp = (__half2*)&u;
#pragma unroll
                    for (int q = 0; q < 4; q++) {
                        float2 fv = __half22float2(hp[q]);
                        int c = cb + q * 2;
                        fv.x = fmaxf(fv.x * bns_s[c] + bnt_s[c], 0.0f);
                        fv.y = fmaxf(fv.y * bns_s[c + 1] + bnt_s[c + 1], 0.0f);
                        hp[q] = __floats2half2_rn(fv.x, fv.y);
                    }
                }
                *(uint4*)&As[stage][row * ASTH + u8] = u;
            }
        } else {
#pragma unroll
            for (int l = 0; l < 4; l++) {
                int f = tid + l * 256;
                int row = f >> 3;
                int c4 = (f & 7) * 4;
                __half2 h0 = __floats2half2_rn(raf[l].x, raf[l].y);
                __half2 h1 = __floats2half2_rn(raf[l].z, raf[l].w);
                uint2 u = { *(unsigned*)&h0, *(unsigned*)&h1 };
                *(uint2*)&As[stage][row * ASTH + c4] = u;
            }
        }
    };

    const int T = K / 32;
    ldA(0); ldB(0);
    stA(0, 0); stB(0);
    if (T > 1) { ldA(1); ldB(1); }
    __syncthreads();

    for (int t = 0; t < T; t++) {
        const __half* as = As[t & 1];
        const __half* bs = Bs[t & 1];
#pragma unroll
        for (int ks = 0; ks < 2; ks++) {
            wmma::fragment<wmma::matrix_a, 16, 16, 16, __half, wmma::row_major> af[2];
            wmma::fragment<wmma::matrix_b, 16, 16, 16, __half, wmma::row_major> bf[4];
#pragma unroll
            for (int i = 0; i < 2; i++)
                wmma::load_matrix_sync(af[i], &as[(wm * 32 + i * 16) * ASTH + ks * 16], ASTH);
#pragma unroll
            for (int j = 0; j < 4; j++)
                wmma::load_matrix_sync(bf[j], &bs[(ks * 16) * BSTH + wn * 64 + j * 16], BSTH);
#pragma unroll
            for (int i = 0; i < 2; i++)
#pragma unroll
                for (int j = 0; j < 4; j++)
                    wmma::mma_sync(acc[i][j], af[i], bf[j], acc[i][j]);
        }
        if (t + 1 < T) {
            stA(t + 1, (t + 1) & 1); stB((t + 1) & 1);   // other buffer: no race
            if (t + 2 < T) { ldA(t + 2); ldB(t + 2); }
            __syncthreads();
        }
    }

    // epilogue: stage fp32 frag, apply dinv-scale or +bias, fp16 16B stores
#pragma unroll
    for (int i = 0; i < 2; i++)
#pragma unroll
        for (int j = 0; j < 4; j++) {
            wmma::store_matrix_sync(&stg[wid][0], acc[i][j], 16, wmma::mem_row_major);
            __syncwarp();
            int base = lane * 8;
            int r = base >> 4;          // 0..15
            int c = base & 15;          // 0 or 8
            const float* sp = &stg[wid][r * 16 + c];
            int row0 = bRow + wm * 32 + i * 16;
            int grow = row0 + r;
            int col0 = bCol + wn * 64 + j * 16;
            __half2 h[4];
            if (ADD_BIAS) {
#pragma unroll
                for (int q = 0; q < 4; q++) {
                    float b0 = Bias[col0 + c + q * 2];
                    float b1 = Bias[col0 + c + q * 2 + 1];
                    h[q] = __floats2half2_rn(sp[q * 2] + b0, sp[q * 2 + 1] + b1);
                }
            } else {
                float dr = g_dinv[grow < NN ? grow : 0];
#pragma unroll
                for (int q = 0; q < 4; q++)
                    h[q] = __floats2half2_rn(sp[q * 2] * dr, sp[q * 2 + 1] * dr);
            }
            *(uint4*)(C + (size_t)grow * M + col0 + c) = *(uint4*)h;
            __syncwarp();
        }
}

// ------- CSR gather aggregation (warp per dst node, H pre-scaled by dinv) ----
// O[d] = dinv[d] * ( H'[d] + sum_{s in nbr(d)} H'[s] ) + bias,  H' = dinv.*H
template <int NV4>   // 4-half groups per lane: C = NV4*128
__global__ void k_agg(const __half* __restrict__ H, __half* __restrict__ O,
                      const float* __restrict__ bias) {
    const int C = NV4 * 128;
    int w = (blockIdx.x * blockDim.x + threadIdx.x) >> 5;
    if (w >= NN) return;
    int lane = threadIdx.x & 31;
    float di = g_dinv[w];

    float4 acc[NV4];
    const uint2* selfp = (const uint2*)(H + (size_t)w * C);
#pragma unroll
    for (int v = 0; v < NV4; v++) {
        uint2 u = selfp[lane + 32 * v];
        float2 a = __half22float2(*(__half2*)&u.x);
        float2 b = __half22float2(*(__half2*)&u.y);
        acc[v] = make_float4(a.x, a.y, b.x, b.y);
    }
    int p = g_rowptr[w], e = g_rowptr[w + 1];
    for (; p + 1 < e; p += 2) {
        int s0 = g_col[p], s1 = g_col[p + 1];
        const uint2* h0 = (const uint2*)(H + (size_t)s0 * C);
        const uint2* h1 = (const uint2*)(H + (size_t)s1 * C);
#pragma unroll
        for (int v = 0; v < NV4; v++) {
            uint2 u0 = h0[lane + 32 * v];
            uint2 u1 = h1[lane + 32 * v];
            float2 a0 = __half22float2(*(__half2*)&u0.x);
            float2 b0 = __half22float2(*(__half2*)&u0.y);
            float2 a1 = __half22float2(*(__half2*)&u1.x);
            float2 b1 = __half22float2(*(__half2*)&u1.y);
            acc[v].x += a0.x + a1.x;
            acc[v].y += a0.y + a1.y;
            acc[v].z += b0.x + b1.x;
            acc[v].w += b0.y + b1.y;
        }
    }
    if (p < e) {
        int s = g_col[p];
        const uint2* hp = (const uint2*)(H + (size_t)s * C);
#pragma unroll
        for (int v = 0; v < NV4; v++) {
            uint2 u = hp[lane + 32 * v];
            float2 a = __half22float2(*(__half2*)&u.x);
            float2 b = __half22float2(*(__half2*)&u.y);
            acc[v].x += a.x; acc[v].y += a.y;
            acc[v].z += b.x; acc[v].w += b.y;
        }
    }
#pragma unroll
    for (int v = 0; v < NV4; v++) {
        int c = (lane + 32 * v) * 4;
        float4 bb = *(const float4*)(bias + c);
        __half2 o0 = __floats2half2_rn(acc[v].x * di + bb.x, acc[v].y * di + bb.y);
        __half2 o1 = __floats2half2_rn(acc[v].z * di + bb.z, acc[v].w * di + bb.w);
        uint2 u = { *(unsigned*)&o0, *(unsigned*)&o1 };
        *(uint2*)(O + (size_t)w * C + c) = u;
    }
}

// ---- layer-1 aggregate-before-transform: X[d] = dinv_d*(Σ dinv_s*f(A[s]) + dinv_d*f(A[d]))
// f(x) = relu(bns[c]*x + bnt[c]).  C = 128 (one uint2 per lane).
__device__ __forceinline__ float4 bnrelu4(uint2 u, float4 sc, float4 tc) {
    float2 a = __half22float2(*(__half2*)&u.x);
    float2 b = __half22float2(*(__half2*)&u.y);
    float4 r;
    r.x = fmaxf(a.x * sc.x + tc.x, 0.0f);
    r.y = fmaxf(a.y * sc.y + tc.y, 0.0f);
    r.z = fmaxf(b.x * sc.z + tc.z, 0.0f);
    r.w = fmaxf(b.y * sc.w + tc.w, 0.0f);
    return r;
}
__global__ void k_aggx(const __half* __restrict__ A0, __half* __restrict__ X) {
    int w = (blockIdx.x * blockDim.x + threadIdx.x) >> 5;
    if (w >= NN) return;
    int lane = threadIdx.x & 31;
    int c4 = lane * 4;
    float di = g_dinv[w];
    float4 sc = *(const float4*)&g_bns[c4];
    float4 tc = *(const float4*)&g_bnt[c4];

    uint2 us = *(const uint2*)(A0 + (size_t)w * 128 + c4);
    float4 fs = bnrelu4(us, sc, tc);
    float4 acc = make_float4(fs.x * di, fs.y * di, fs.z * di, fs.w * di);

    int p = g_rowptr[w], e = g_rowptr[w + 1];
    for (; p + 1 < e; p += 2) {
        int s0 = g_col[p], s1 = g_col[p + 1];
        float d0 = g_dinv[s0], d1 = g_dinv[s1];
        uint2 u0 = *(const uint2*)(A0 + (size_t)s0 * 128 + c4);
        uint2 u1 = *(const uint2*)(A0 + (size_t)s1 * 128 + c4);
        float4 f0 = bnrelu4(u0, sc, tc);
        float4 f1 = bnrelu4(u1, sc, tc);
        acc.x += d0 * f0.x + d1 * f1.x;
        acc.y += d0 * f0.y + d1 * f1.y;
        acc.z += d0 * f0.z + d1 * f1.z;
        acc.w += d0 * f0.w + d1 * f1.w;
    }
    if (p < e) {
        int s = g_col[p];
        float ds = g_dinv[s];
        uint2 u = *(const uint2*)(A0 + (size_t)s * 128 + c4);
        float4 f = bnrelu4(u, sc, tc);
        acc.x += ds * f.x; acc.y += ds * f.y;
        acc.z += ds * f.z; acc.w += ds * f.w;
    }
    __half2 o0 = __floats2half2_rn(acc.x * di, acc.y * di);
    __half2 o1 = __floats2half2_rn(acc.z * di, acc.w * di);
    uint2 u = { *(unsigned*)&o0, *(unsigned*)&o1 };
    *(uint2*)(X + (size_t)w * 128 + c4) = u;
}

// ---------------- BatchNorm stats (training-mode, biased var) ----------------
__global__ void k_bnzero() {
    int c = threadIdx.x;   // 256 threads
    g_bnsum[c] = 0.0; g_bnsumsq[c] = 0.0;
}

#define BN_P 512   // row-partials per channel
__global__ void k_bnstats(const __half* __restrict__ h, int C) {
    int t = blockIdx.x * blockDim.x + threadIdx.x;
    if (t >= C * BN_P) return;
    int c = t & (C - 1);
    int p = t / C;
    float s = 0.f, q = 0.f;
    for (int r = p; r < NN; r += BN_P) {
        float x = __half2float(h[(size_t)r * C + c]);
        s += x; q += x * x;
    }
    atomicAdd(&g_bnsum[c], (double)s);
    atomicAdd(&g_bnsumsq[c], (double)q);
}

__global__ void k_bnfin(const float* __restrict__ gamma,
                        const float* __restrict__ beta, int C) {
    int c = blockIdx.x * blockDim.x + threadIdx.x;
    if (c >= C) return;
    double m = g_bnsum[c] / (double)NN;
    double v = g_bnsumsq[c] / (double)NN - m * m;
    float sc = gamma[c] * rsqrtf((float)v + BN_EPS);
    g_bns[c] = sc;
    g_bnt[c] = beta[c] - (float)m * sc;
}

// ---------------- global mean pool (sorted batch -> contiguous ranges) -------
__global__ void k_bounds(const int* __restrict__ batch) {
    int g = threadIdx.x;            // 0..NG (65 threads)
    if (g > NG) return;
    int lo = 0, hi = NN;            // lower_bound of g
    while (lo < hi) { int mid = (lo + hi) >> 1; if (batch[mid] < g) lo = mid + 1; else hi = mid; }
    g_gstart[g] = lo;
}

// pool applies layer-2 BN + ReLU on the fly (A holds pre-BN values)
__global__ void k_pool(const __half* __restrict__ h) {
    int b = blockIdx.x;             // 64 blocks, 256 threads
    int c = threadIdx.x;
    int st = g_gstart[b], en = g_gstart[b + 1];
    float sc = g_bns[c], sh = g_bnt[c];
    float s = 0.f;
    for (int r = st; r < en; r++) {
        float x = __half2float(h[(size_t)r * 256 + c]);
        s += fmaxf(x * sc + sh, 0.0f);
    }
    g_pool[b * 256 + c] = s / fmaxf((float)(en - st), 1.0f);
}

// ---------------- FC head ----------------
__global__ void k_fc1(const float* __restrict__ Wf0, const float* __restrict__ bf0) {
    int t = blockIdx.x * blockDim.x + threadIdx.x;
    if (t >= NG * 1024) return;
    int b = t >> 10, j = t & 1023;
    float s = bf0[j];
    const float* g = g_pool + b * 256;
    for (int c = 0; c < 256; c++) s += g[c] * Wf0[c * 1024 + j];
    g_fc1[t] = fmaxf(s, 0.0f);
}

__global__ void k_fc2(const float* __restrict__ Wf1, const float* __restrict__ bf1,
                      float* __restrict__ out) {
    int t = blockIdx.x * blockDim.x + threadIdx.x;
    if (t >= NG * 128) return;
    int b = t >> 7, j = t & 127;
    float s = bf1[j];
    const float* g = g_fc1 + b * 1024;
    for (int c = 0; c < 1024; c++) s += g[c] * Wf1[c * 128 + j];
    out[t] = s;
}

// ---------------- launcher ----------------
extern "C" void kernel_launch(void* const* d_in, const int* in_sizes, int n_in,
                              void* d_out, int out_size) {
    const float* x     = (const float*)d_in[0];
    const int*   ei    = (const int*)d_in[1];
    const int*   batch = (const int*)d_in[2];
    const float* Wg0 = (const float*)d_in[3];
    const float* bg0 = (const float*)d_in[4];
    const float* gm0 = (const float*)d_in[5];
    const float* bt0 = (const float*)d_in[6];
    const float* Wg1 = (const float*)d_in[7];
    const float* bg1 = (const float*)d_in[8];
    const float* gm1 = (const float*)d_in[9];
    const float* bt1 = (const float*)d_in[10];
    const float* Wg2 = (const float*)d_in[11];
    const float* bg2 = (const float*)d_in[12];
    const float* gm2 = (const float*)d_in[13];
    const float* bt2 = (const float*)d_in[14];
    const float* Wf0 = (const float*)d_in[15];
    const float* bf0 = (const float*)d_in[16];
    const float* Wf1 = (const float*)d_in[17];
    const float* bf1 = (const float*)d_in[18];
    float* out = (float*)d_out;

    const int* src = ei;           // edge_index[0]
    const int* dst = ei + NE;      // edge_index[1]

    __half* H; cudaGetSymbolAddress((void**)&H, g_H);
    __half* A; cudaGetSymbolAddress((void**)&A, g_A);

    // side stream + fork/join events, created once on first (uncaptured) call
    static cudaStream_t s_side = nullptr;
    static cudaEvent_t  e_dinv = nullptr, e_csr = nullptr;
    if (!s_side) {
        cudaStreamCreateWithFlags(&s_side, cudaStreamNonBlocking);
        cudaEventCreateWithFlags(&e_dinv, cudaEventDisableTiming);
        cudaEventCreateWithFlags(&e_csr, cudaEventDisableTiming);
    }

    const int NBLK = (NN + 1023) / 1024;   // 49

    // ---- main stream: degree + dinv (needed by GEMM-0 epilogue) ----
    k_prep<<<(NN + 255) / 256, 256>>>();
    k_deg_count<<<(NE + 255) / 256, 256>>>(dst);
    k_dinv<<<(NN + 255) / 256, 256>>>();
    cudaEventRecord(e_dinv, 0);

    // ---- side stream: CSR build + graph bounds, concurrent with GEMM-0 ----
    cudaStreamWaitEvent(s_side, e_dinv, 0);
    k_scan1<<<NBLK, 1024, 0, s_side>>>();
    k_scan2<<<1, 32, 0, s_side>>>(NBLK);
    k_scan3<<<NBLK, 1024, 0, s_side>>>();
    k_csr<<<(NE + 255) / 256, 256, 0, s_side>>>(src, dst);
    k_bounds<<<1, 96, 0, s_side>>>(batch);
    cudaEventRecord(e_csr, s_side);

    const int gy = NNP / 128;   // 391

    // ---- layer 0 (transform-first): H = dinv .* (x @ Wg0)  [overlaps CSR build]
    k_gemm_h<0, 0, 0><<<dim3(1, gy), 256>>>(x, Wg0, nullptr, H, NN, 1280, 128);
    cudaStreamWaitEvent(0, e_csr, 0);          // join: agg needs CSR
    k_agg<1><<<(NN * 32 + 255) / 256, 256>>>(H, A, bg0);
    k_bnzero<<<1, 256>>>();
    k_bnstats<<<(128 * BN_P + 255) / 256, 256>>>(A, 128);
    k_bnfin<<<1, 128>>>(gm0, bt0, 128);

    // ---- layer 1 (aggregate-first): X = agg(relu(bn0(A0))); A1 = X @ Wg1 + b1
    k_aggx<<<(NN * 32 + 255) / 256, 256>>>(A, H);
    k_gemm_h<1, 0, 1><<<dim3(2, gy), 256>>>(H, Wg1, bg1, A, NN, 128, 256);
    k_bnzero<<<1, 256>>>();
    k_bnstats<<<(256 * BN_P + 255) / 256, 256>>>(A, 256);
    k_bnfin<<<1, 256>>>(gm1, bt1, 256);

    // ---- layer 2 (transform-first): H = dinv .* (relu(bn1(A1)) @ Wg2); A2 = agg(H)+b2
    k_gemm_h<1, 1, 0><<<dim3(2, gy), 256>>>(A, Wg2, nullptr, H, NNP, 256, 256);
    k_agg<2><<<(NN * 32 + 255) / 256, 256>>>(H, A, bg2);
    k_bnzero<<<1, 256>>>();
    k_bnstats<<<(256 * BN_P + 255) / 256, 256>>>(A, 256);
    k_bnfin<<<1, 256>>>(gm2, bt2, 256);

    // ---- pool (applies bn2 + relu) + FC head
    k_pool<<<NG, 256>>>(A);
    k_fc1<<<(NG * 1024 + 255) / 256, 256>>>(Wf0, bf0);
    k_fc2<<<(NG * 128 + 255) / 256, 256>>>(Wf1, bf1, out);
}

// round 16
// speedup vs baseline: 3.3353x; 1.0787x over previous
#include <cuda_runtime.h>
#include <cuda_fp16.h>
#include <mma.h>
#include <math.h>
#include <cstdint>

using namespace nvcuda;

#define NN 50000
#define NNP 50048           // 391 * 128, padded row count for GEMM tiles
#define NE 1600000
#define NG 64
#define BN_EPS 1e-5f

// ---------------- scratch (static __device__, no allocation) ----------------
__device__ float  g_deg[NN];
__device__ float  g_dinv[NN];
__device__ int    g_rowptr[NN + 1];
__device__ int    g_cursor[NN];
__device__ int    g_col[NE];
__device__ int    g_blksum[64];
__device__ int    g_blkoff[64];
__device__ int    g_gstart[NG + 1];
__device__ __half g_H[(size_t)NNP * 256];   // GEMM output / layer-1 Xagg
__device__ __half g_A[(size_t)NNP * 256];   // conv output (pre-BN), fp16
__device__ __half g_W0h[1280 * 128];        // fp16 weights (pre-converted)
__device__ __half g_W1h[128 * 256];
__device__ __half g_W2h[256 * 256];
__device__ double g_bnsum[256];
__device__ double g_bnsumsq[256];
__device__ __align__(16) float g_bns[256];  // BN scale (current layer)
__device__ __align__(16) float g_bnt[256];  // BN shift (current layer)
__device__ float  g_pool[NG * 256];
__device__ float  g_fc1[NG * 1024];

// ---------------- init / degree / BN-accumulator zero ----------------
__global__ void k_prep() {
    int i = blockIdx.x * blockDim.x + threadIdx.x;
    if (i < NN) g_deg[i] = 1.0f;
    if (i < 256) { g_bnsum[i] = 0.0; g_bnsumsq[i] = 0.0; }
}

__global__ void k_deg_count(const int* __restrict__ dst) {
    int e = blockIdx.x * blockDim.x + threadIdx.x;
    if (e < NE) atomicAdd(&g_deg[dst[e]], 1.0f);
}

__global__ void k_dinv() {
    int i = blockIdx.x * blockDim.x + threadIdx.x;
    if (i < NN) g_dinv[i] = rsqrtf(g_deg[i]);   // deg >= 1 always (self loop)
}

// ---------------- weight fp32 -> fp16 (once per call, off critical path) ----
__global__ void k_wconv(const float* __restrict__ w, __half* __restrict__ o, int n8) {
    int i = blockIdx.x * blockDim.x + threadIdx.x;   // one uint4 out per thread
    if (i >= n8) return;
    const float4* wp = (const float4*)w + i * 2;
    float4 a = wp[0], b = wp[1];
    __half2 h[4] = { __floats2half2_rn(a.x, a.y), __floats2half2_rn(a.z, a.w),
                     __floats2half2_rn(b.x, b.y), __floats2half2_rn(b.z, b.w) };
    *(uint4*)(o + (size_t)i * 8) = *(uint4*)h;
}

// ---------------- 3-phase exclusive scan of (deg-1) -> rowptr ----------------
__global__ void k_scan1() {
    __shared__ int sh[1024];
    int tid = threadIdx.x;
    int i = blockIdx.x * 1024 + tid;
    int v = (i < NN) ? ((int)g_deg[i] - 1) : 0;
    sh[tid] = v;
    __syncthreads();
    for (int off = 1; off < 1024; off <<= 1) {
        int t = (tid >= off) ? sh[tid - off] : 0;
        __syncthreads();
        sh[tid] += t;
        __syncthreads();
    }
    if (i < NN) g_rowptr[i] = sh[tid] - v;     // block-local exclusive
    if (tid == 1023) g_blksum[blockIdx.x] = sh[1023];
}
__global__ void k_scan2(int nblk) {
    if (threadIdx.x != 0) return;
    int acc = 0;
    for (int b = 0; b < nblk; b++) { g_blkoff[b] = acc; acc += g_blksum[b]; }
    g_rowptr[NN] = acc;
}
__global__ void k_scan3() {
    int i = blockIdx.x * 1024 + threadIdx.x;
    if (i < NN) {
        int r = g_rowptr[i] + g_blkoff[blockIdx.x];
        g_rowptr[i] = r;
        g_cursor[i] = r;           // csr atomics return slot directly
    }
}

__global__ void k_csr(const int* __restrict__ src, const int* __restrict__ dst) {
    int e = blockIdx.x * blockDim.x + threadIdx.x;
    if (e >= NE) return;
    int p = atomicAdd(&g_cursor[dst[e]], 1);
    g_col[p] = src[e];
}

// ---- fp16 HMMA GEMM (m16n16k16), double-buffered smem + reg prefetch ------
// C[NNP,M](fp16) = epi( bn(A[*,K]) @ B[K,M] ),  B is fp16 (pre-converted)
// A_HALF=0: A fp32 raw.  A_HALF=1: A fp16.
// BN_IN=1: apply y = relu(bns[c]*x + bnt[c]) to A elements on load.
// ADD_BIAS=1: epilogue adds Bias[col]; else epilogue scales row by g_dinv[row].
// Rows >= NA clamp to row 0 (garbage only in never-read pad rows).
#define ASTH 40    // As row stride in halves (32 + 8 pad)
#define BSTH 136   // Bs row stride in halves (128 + 8 pad)
template <int A_HALF, int BN_IN, int ADD_BIAS>
__global__ __launch_bounds__(256) void k_gemm_h(const void* __restrict__ Aptr,
                                                const __half* __restrict__ B,
                                                const float* __restrict__ Bias,
                                                __half* __restrict__ C,
                                                int NA, int K, int M) {
    __shared__ __half As[2][128 * ASTH];
    __shared__ __half Bs[2][32 * BSTH];
    __shared__ float  stg[8][16 * 16 + 8];
    __shared__ float  bns_s[256], bnt_s[256];
    const int bRow = blockIdx.y * 128;
    const int bCol = blockIdx.x * 128;
    const int tid = threadIdx.x;
    const int wid = tid >> 5;
    const int lane = tid & 31;
    const int wm = wid & 3;
    const int wn = wid >> 2;

    if (BN_IN) {
        for (int i = tid; i < K; i += 256) { bns_s[i] = g_bns[i]; bnt_s[i] = g_bnt[i]; }
        __syncthreads();   // bns_s/bnt_s visible to all threads before stA(0,0)
    }

    wmma::fragment<wmma::accumulator, 16, 16, 16, float> acc[2][4];
#pragma unroll
    for (int i = 0; i < 2; i++)
#pragma unroll
        for (int j = 0; j < 4; j++) wmma::fill_fragment(acc[i][j], 0.0f);

    // prefetch registers
    uint4  rbh[2];           // B tile: 32x128 half = 512 uint4, 2/thread
    float4 raf[4];           // A fp32: 128x32 fp32 = 1024 float4, 4/thread
    uint4  rah[2];           // A fp16: 128x32 half = 512 uint4, 2/thread

    auto ldB = [&](int t) {
        int k0 = t * 32;
#pragma unroll
        for (int l = 0; l < 2; l++) {
            int f = tid + l * 256;
            int row = f >> 4;              // 0..31 (16 uint4 per row)
            int c8 = (f & 15) * 8;
            rbh[l] = *(const uint4*)(B + (size_t)(k0 + row) * M + bCol + c8);
        }
    };
    auto stB = [&](int stage) {
#pragma unroll
        for (int l = 0; l < 2; l++) {
            int f = tid + l * 256;
            int row = f >> 4;
            int c8 = (f & 15) * 8;
            *(uint4*)&Bs[stage][row * BSTH + c8] = rbh[l];
        }
    };
    auto ldA = [&](int t) {
        int k0 = t * 32;
        if (A_HALF) {
            const __half* A = (const __half*)Aptr;
#pragma unroll
            for (int l = 0; l < 2; l++) {
                int f = tid + l * 256;
                int row = f >> 2;          // 0..127
                int u8 = (f & 3) * 8;      // half offset within row
                int gRow = bRow + row;
                if (gRow >= NA) gRow = 0;
                rah[l] = *(const uint4*)(A + (size_t)gRow * K + k0 + u8);
            }
        } else {
            const float* A = (const float*)Aptr;
#pragma unroll
            for (int l = 0; l < 4; l++) {
                int f = tid + l * 256;
                int row = f >> 3;          // 0..127 (8 float4 per row)
                int c4 = (f & 7) * 4;
                int gRow = bRow + row;
                if (gRow >= NA) gRow = 0;
                raf[l] = *(const float4*)(A + (size_t)gRow * K + k0 + c4);
            }
        }
    };
    auto stA = [&](int t, int stage) {
        if (A_HALF) {
            int k0 = t * 32;
#pragma unroll
            for (int l = 0; l < 2; l++) {
                int f = tid + l * 256;
                int row = f >> 2;
                int u8 = (f & 3) * 8;
                uint4 u = rah[l];
                if (BN_IN) {
                    int cb = k0 + u8;
                    __half2* hp = (__half2*)&u;
#pragma unroll
                    for (int q = 0; q < 4; q++) {
                        float2 fv = __half22float2(hp[q]);
                        int c = cb + q * 2;
                        fv.x = fmaxf(fv.x * bns_s[c] + bnt_s[c], 0.0f);
                        fv.y = fmaxf(fv.y * bns_s[c + 1] + bnt_s[c + 1], 0.0f);
                        hp[q] = __floats2half2_rn(fv.x, fv.y);
                    }
                }
                *(uint4*)&As[stage][row * ASTH + u8] = u;
            }
        } else {
#pragma unroll
            for (int l = 0; l < 4; l++) {
                int f = tid + l * 256;
                int row = f >> 3;
                int c4 = (f & 7) * 4;
                __half2 h0 = __floats2half2_rn(raf[l].x, raf[l].y);
                __half2 h1 = __floats2half2_rn(raf[l].z, raf[l].w);
                uint2 u = { *(unsigned*)&h0, *(unsigned*)&h1 };
                *(uint2*)&As[stage][row * ASTH + c4] = u;
            }
        }
    };

    const int T = K / 32;
    ldA(0); ldB(0);
    stA(0, 0); stB(0);
    if (T > 1) { ldA(1); ldB(1); }
    __syncthreads();

    for (int t = 0; t < T; t++) {
        const __half* as = As[t & 1];
        const __half* bs = Bs[t & 1];
#pragma unroll
        for (int ks = 0; ks < 2; ks++) {
            wmma::fragment<wmma::matrix_a, 16, 16, 16, __half, wmma::row_major> af[2];
            wmma::fragment<wmma::matrix_b, 16, 16, 16, __half, wmma::row_major> bf[4];
#pragma unroll
            for (int i = 0; i < 2; i++)
                wmma::load_matrix_sync(af[i], &as[(wm * 32 + i * 16) * ASTH + ks * 16], ASTH);
#pragma unroll
            for (int j = 0; j < 4; j++)
                wmma::load_matrix_sync(bf[j], &bs[(ks * 16) * BSTH + wn * 64 + j * 16], BSTH);
#pragma unroll
            for (int i = 0; i < 2; i++)
#pragma unroll
                for (int j = 0; j < 4; j++)
                    wmma::mma_sync(acc[i][j], af[i], bf[j], acc[i][j]);
        }
        if (t + 1 < T) {
            stA(t + 1, (t + 1) & 1); stB((t + 1) & 1);   // other buffer: no race
            if (t + 2 < T) { ldA(t + 2); ldB(t + 2); }
            __syncthreads();
        }
    }

    // epilogue: stage fp32 frag, apply dinv-scale or +bias, fp16 16B stores
#pragma unroll
    for (int i = 0; i < 2; i++)
#pragma unroll
        for (int j = 0; j < 4; j++) {
            wmma::store_matrix_sync(&stg[wid][0], acc[i][j], 16, wmma::mem_row_major);
            __syncwarp();
            int base = lane * 8;
            int r = base >> 4;          // 0..15
            int c = base & 15;          // 0 or 8
            const float* sp = &stg[wid][r * 16 + c];
            int row0 = bRow + wm * 32 + i * 16;
            int grow = row0 + r;
            int col0 = bCol + wn * 64 + j * 16;
            __half2 h[4];
            if (ADD_BIAS) {
#pragma unroll
                for (int q = 0; q < 4; q++) {
                    float b0 = Bias[col0 + c + q * 2];
                    float b1 = Bias[col0 + c + q * 2 + 1];
                    h[q] = __floats2half2_rn(sp[q * 2] + b0, sp[q * 2 + 1] + b1);
                }
            } else {
                float dr = g_dinv[grow < NN ? grow : 0];
#pragma unroll
                for (int q = 0; q < 4; q++)
                    h[q] = __floats2half2_rn(sp[q * 2] * dr, sp[q * 2 + 1] * dr);
            }
            *(uint4*)(C + (size_t)grow * M + col0 + c) = *(uint4*)h;
            __syncwarp();
        }
}

// ------- CSR gather aggregation (warp per dst node, H pre-scaled by dinv) ----
// O[d] = dinv[d] * ( H'[d] + sum_{s in nbr(d)} H'[s] ) + bias,  H' = dinv.*H
template <int NV4>   // 4-half groups per lane: C = NV4*128
__global__ void k_agg(const __half* __restrict__ H, __half* __restrict__ O,
                      const float* __restrict__ bias) {
    const int C = NV4 * 128;
    int w = (blockIdx.x * blockDim.x + threadIdx.x) >> 5;
    if (w >= NN) return;
    int lane = threadIdx.x & 31;
    float di = g_dinv[w];

    float4 acc[NV4];
    const uint2* selfp = (const uint2*)(H + (size_t)w * C);
#pragma unroll
    for (int v = 0; v < NV4; v++) {
        uint2 u = selfp[lane + 32 * v];
        float2 a = __half22float2(*(__half2*)&u.x);
        float2 b = __half22float2(*(__half2*)&u.y);
        acc[v] = make_float4(a.x, a.y, b.x, b.y);
    }
    int p = g_rowptr[w], e = g_rowptr[w + 1];
    for (; p + 1 < e; p += 2) {
        int s0 = g_col[p], s1 = g_col[p + 1];
        const uint2* h0 = (const uint2*)(H + (size_t)s0 * C);
        const uint2* h1 = (const uint2*)(H + (size_t)s1 * C);
#pragma unroll
        for (int v = 0; v < NV4; v++) {
            uint2 u0 = h0[lane + 32 * v];
            uint2 u1 = h1[lane + 32 * v];
            float2 a0 = __half22float2(*(__half2*)&u0.x);
            float2 b0 = __half22float2(*(__half2*)&u0.y);
            float2 a1 = __half22float2(*(__half2*)&u1.x);
            float2 b1 = __half22float2(*(__half2*)&u1.y);
            acc[v].x += a0.x + a1.x;
            acc[v].y += a0.y + a1.y;
            acc[v].z += b0.x + b1.x;
            acc[v].w += b0.y + b1.y;
        }
    }
    if (p < e) {
        int s = g_col[p];
        const uint2* hp = (const uint2*)(H + (size_t)s * C);
#pragma unroll
        for (int v = 0; v < NV4; v++) {
            uint2 u = hp[lane + 32 * v];
            float2 a = __half22float2(*(__half2*)&u.x);
            float2 b = __half22float2(*(__half2*)&u.y);
            acc[v].x += a.x; acc[v].y += a.y;
            acc[v].z += b.x; acc[v].w += b.y;
        }
    }
#pragma unroll
    for (int v = 0; v < NV4; v++) {
        int c = (lane + 32 * v) * 4;
        float4 bb = *(const float4*)(bias + c);
        __half2 o0 = __floats2half2_rn(acc[v].x * di + bb.x, acc[v].y * di + bb.y);
        __half2 o1 = __floats2half2_rn(acc[v].z * di + bb.z, acc[v].w * di + bb.w);
        uint2 u = { *(unsigned*)&o0, *(unsigned*)&o1 };
        *(uint2*)(O + (size_t)w * C + c) = u;
    }
}

// ---- layer-1 aggregate-before-transform: X[d] = dinv_d*(Σ dinv_s*f(A[s]) + dinv_d*f(A[d]))
// f(x) = relu(bns[c]*x + bnt[c]).  C = 128 (one uint2 per lane).
__device__ __forceinline__ float4 bnrelu4(uint2 u, float4 sc, float4 tc) {
    float2 a = __half22float2(*(__half2*)&u.x);
    float2 b = __half22float2(*(__half2*)&u.y);
    float4 r;
    r.x = fmaxf(a.x * sc.x + tc.x, 0.0f);
    r.y = fmaxf(a.y * sc.y + tc.y, 0.0f);
    r.z = fmaxf(b.x * sc.z + tc.z, 0.0f);
    r.w = fmaxf(b.y * sc.w + tc.w, 0.0f);
    return r;
}
__global__ void k_aggx(const __half* __restrict__ A0, __half* __restrict__ X) {
    int w = (blockIdx.x * blockDim.x + threadIdx.x) >> 5;
    if (w >= NN) return;
    int lane = threadIdx.x & 31;
    int c4 = lane * 4;
    float di = g_dinv[w];
    float4 sc = *(const float4*)&g_bns[c4];
    float4 tc = *(const float4*)&g_bnt[c4];

    uint2 us = *(const uint2*)(A0 + (size_t)w * 128 + c4);
    float4 fs = bnrelu4(us, sc, tc);
    float4 acc = make_float4(fs.x * di, fs.y * di, fs.z * di, fs.w * di);

    int p = g_rowptr[w], e = g_rowptr[w + 1];
    for (; p + 1 < e; p += 2) {
        int s0 = g_col[p], s1 = g_col[p + 1];
        float d0 = g_dinv[s0], d1 = g_dinv[s1];
        uint2 u0 = *(const uint2*)(A0 + (size_t)s0 * 128 + c4);
        uint2 u1 = *(const uint2*)(A0 + (size_t)s1 * 128 + c4);
        float4 f0 = bnrelu4(u0, sc, tc);
        float4 f1 = bnrelu4(u1, sc, tc);
        acc.x += d0 * f0.x + d1 * f1.x;
        acc.y += d0 * f0.y + d1 * f1.y;
        acc.z += d0 * f0.z + d1 * f1.z;
        acc.w += d0 * f0.w + d1 * f1.w;
    }
    if (p < e) {
        int s = g_col[p];
        float ds = g_dinv[s];
        uint2 u = *(const uint2*)(A0 + (size_t)s * 128 + c4);
        float4 f = bnrelu4(u, sc, tc);
        acc.x += ds * f.x; acc.y += ds * f.y;
        acc.z += ds * f.z; acc.w += ds * f.w;
    }
    __half2 o0 = __floats2half2_rn(acc.x * di, acc.y * di);
    __half2 o1 = __floats2half2_rn(acc.z * di, acc.w * di);
    uint2 u = { *(unsigned*)&o0, *(unsigned*)&o1 };
    *(uint2*)(X + (size_t)w * 128 + c4) = u;
}

// ---------------- BatchNorm stats (training-mode, biased var) ----------------
#define BN_P 512   // row-partials per channel
__global__ void k_bnstats(const __half* __restrict__ h, int C) {
    int t = blockIdx.x * blockDim.x + threadIdx.x;
    if (t >= C * BN_P) return;
    int c = t & (C - 1);
    int p = t / C;
    float s = 0.f, q = 0.f;
    for (int r = p; r < NN; r += BN_P) {
        float x = __half2float(h[(size_t)r * C + c]);
        s += x; q += x * x;
    }
    atomicAdd(&g_bnsum[c], (double)s);
    atomicAdd(&g_bnsumsq[c], (double)q);
}

// consumes accumulators, then resets them for the next layer
__global__ void k_bnfin(const float* __restrict__ gamma,
                        const float* __restrict__ beta, int C) {
    int c = blockIdx.x * blockDim.x + threadIdx.x;
    if (c >= C) return;
    double m = g_bnsum[c] / (double)NN;
    double v = g_bnsumsq[c] / (double)NN - m * m;
    float sc = gamma[c] * rsqrtf((float)v + BN_EPS);
    g_bns[c] = sc;
    g_bnt[c] = beta[c] - (float)m * sc;
    g_bnsum[c] = 0.0;
    g_bnsumsq[c] = 0.0;
}

// ---------------- global mean pool (sorted batch -> contiguous ranges) -------
__global__ void k_bounds(const int* __restrict__ batch) {
    int g = threadIdx.x;            // 0..NG (65 threads)
    if (g > NG) return;
    int lo = 0, hi = NN;            // lower_bound of g
    while (lo < hi) { int mid = (lo + hi) >> 1; if (batch[mid] < g) lo = mid + 1; else hi = mid; }
    g_gstart[g] = lo;
}

// pool applies layer-2 BN + ReLU on the fly (A holds pre-BN values)
__global__ void k_pool(const __half* __restrict__ h) {
    int b = blockIdx.x;             // 64 blocks, 256 threads
    int c = threadIdx.x;
    int st = g_gstart[b], en = g_gstart[b + 1];
    float sc = g_bns[c], sh = g_bnt[c];
    float s = 0.f;
    for (int r = st; r < en; r++) {
        float x = __half2float(h[(size_t)r * 256 + c]);
        s += fmaxf(x * sc + sh, 0.0f);
    }
    g_pool[b * 256 + c] = s / fmaxf((float)(en - st), 1.0f);
}

// ---------------- FC head ----------------
__global__ void k_fc1(const float* __restrict__ Wf0, const float* __restrict__ bf0) {
    int t = blockIdx.x * blockDim.x + threadIdx.x;
    if (t >= NG * 1024) return;
    int b = t >> 10, j = t & 1023;
    float s = bf0[j];
    const float* g = g_pool + b * 256;
    for (int c = 0; c < 256; c++) s += g[c] * Wf0[c * 1024 + j];
    g_fc1[t] = fmaxf(s, 0.0f);
}

__global__ void k_fc2(const float* __restrict__ Wf1, const float* __restrict__ bf1,
                      float* __restrict__ out) {
    int t = blockIdx.x * blockDim.x + threadIdx.x;
    if (t >= NG * 128) return;
    int b = t >> 7, j = t & 127;
    float s = bf1[j];
    const float* g = g_fc1 + b * 1024;
    for (int c = 0; c < 1024; c++) s += g[c] * Wf1[c * 128 + j];
    out[t] = s;
}

// ---------------- launcher ----------------
extern "C" void kernel_launch(void* const* d_in, const int* in_sizes, int n_in,
                              void* d_out, int out_size) {
    const float* x     = (const float*)d_in[0];
    const int*   ei    = (const int*)d_in[1];
    const int*   batch = (const int*)d_in[2];
    const float* Wg0 = (const float*)d_in[3];
    const float* bg0 = (const float*)d_in[4];
    const float* gm0 = (const float*)d_in[5];
    const float* bt0 = (const float*)d_in[6];
    const float* Wg1 = (const float*)d_in[7];
    const float* bg1 = (const float*)d_in[8];
    const float* gm1 = (const float*)d_in[9];
    const float* bt1 = (const float*)d_in[10];
    const float* Wg2 = (const float*)d_in[11];
    const float* bg2 = (const float*)d_in[12];
    const float* gm2 = (const float*)d_in[13];
    const float* bt2 = (const float*)d_in[14];
    const float* Wf0 = (const float*)d_in[15];
    const float* bf0 = (const float*)d_in[16];
    const float* Wf1 = (const float*)d_in[17];
    const float* bf1 = (const float*)d_in[18];
    float* out = (float*)d_out;

    const int* src = ei;           // edge_index[0]
    const int* dst = ei + NE;      // edge_index[1]

    __half* H; cudaGetSymbolAddress((void**)&H, g_H);
    __half* A; cudaGetSymbolAddress((void**)&A, g_A);
    __half* W0h; cudaGetSymbolAddress((void**)&W0h, g_W0h);
    __half* W1h; cudaGetSymbolAddress((void**)&W1h, g_W1h);
    __half* W2h; cudaGetSymbolAddress((void**)&W2h, g_W2h);

    // side stream + fork/join events, created once on first (uncaptured) call
    static cudaStream_t s_side = nullptr;
    static cudaEvent_t  e_fork = nullptr, e_dinv = nullptr, e_csr = nullptr, e_w = nullptr;
    if (!s_side) {
        cudaStreamCreateWithFlags(&s_side, cudaStreamNonBlocking);
        cudaEventCreateWithFlags(&e_fork, cudaEventDisableTiming);
        cudaEventCreateWithFlags(&e_dinv, cudaEventDisableTiming);
        cudaEventCreateWithFlags(&e_csr, cudaEventDisableTiming);
        cudaEventCreateWithFlags(&e_w, cudaEventDisableTiming);
    }

    const int NBLK = (NN + 1023) / 1024;   // 49

    // ---- fork: side stream joins capture by waiting on main-stream event ----
    cudaEventRecord(e_fork, 0);
    cudaStreamWaitEvent(s_side, e_fork, 0);

    // ---- side stream: weight conversion (overlaps prep/deg/dinv on main) ----
    k_wconv<<<(1280 * 128 / 8 + 255) / 256, 256, 0, s_side>>>(Wg0, W0h, 1280 * 128 / 8);
    k_wconv<<<(128 * 256 / 8 + 255) / 256, 256, 0, s_side>>>(Wg1, W1h, 128 * 256 / 8);
    k_wconv<<<(256 * 256 / 8 + 255) / 256, 256, 0, s_side>>>(Wg2, W2h, 256 * 256 / 8);
    cudaEventRecord(e_w, s_side);

    // ---- main stream: degree + dinv (needed by GEMM-0 epilogue) ----
    k_prep<<<(NN + 255) / 256, 256>>>();
    k_deg_count<<<(NE + 255) / 256, 256>>>(dst);
    k_dinv<<<(NN + 255) / 256, 256>>>();
    cudaEventRecord(e_dinv, 0);

    // ---- side stream: CSR build + graph bounds, concurrent with GEMM-0 ----
    cudaStreamWaitEvent(s_side, e_dinv, 0);
    k_scan1<<<NBLK, 1024, 0, s_side>>>();
    k_scan2<<<1, 32, 0, s_side>>>(NBLK);
    k_scan3<<<NBLK, 1024, 0, s_side>>>();
    k_csr<<<(NE + 255) / 256, 256, 0, s_side>>>(src, dst);
    k_bounds<<<1, 96, 0, s_side>>>(batch);
    cudaEventRecord(e_csr, s_side);

    const int gy = NNP / 128;   // 391

    // ---- layer 0 (transform-first): H = dinv .* (x @ Wg0)  [overlaps CSR build]
    cudaStreamWaitEvent(0, e_w, 0);            // GEMM-0 needs fp16 weights
    k_gemm_h<0, 0, 0><<<dim3(1, gy), 256>>>(x, W0h, nullptr, H, NN, 1280, 128);
    cudaStreamWaitEvent(0, e_csr, 0);          // join: agg needs CSR
    k_agg<1><<<(NN * 32 + 255) / 256, 256>>>(H, A, bg0);
    k_bnstats<<<(128 * BN_P + 255) / 256, 256>>>(A, 128);
    k_bnfin<<<1, 128>>>(gm0, bt0, 128);

    // ---- layer 1 (aggregate-first): X = agg(relu(bn0(A0))); A1 = X @ Wg1 + b1
    k_aggx<<<(NN * 32 + 255) / 256, 256>>>(A, H);
    k_gemm_h<1, 0, 1><<<dim3(2, gy), 256>>>(H, W1h, bg1, A, NN, 128, 256);
    k_bnstats<<<(256 * BN_P + 255) / 256, 256>>>(A, 256);
    k_bnfin<<<1, 256>>>(gm1, bt1, 256);

    // ---- layer 2 (transform-first): H = dinv .* (relu(bn1(A1)) @ Wg2); A2 = agg(H)+b2
    k_gemm_h<1, 1, 0><<<dim3(2, gy), 256>>>(A, W2h, nullptr, H, NNP, 256, 256);
    k_agg<2><<<(NN * 32 + 255) / 256, 256>>>(H, A, bg2);
    k_bnstats<<<(256 * BN_P + 255) / 256, 256>>>(A, 256);
    k_bnfin<<<1, 256>>>(gm2, bt2, 256);

    // ---- pool (applies bn2 + relu) + FC head
    k_pool<<<NG, 256>>>(A);
    k_fc1<<<(NG * 1024 + 255) / 256, 256>>>(Wf0, bf0);
    k_fc2<<<(NG * 128 + 255) / 256, 256>>>(Wf1, bf1, out);
}